// round 1
// baseline (speedup 1.0000x reference)
#include <cuda_runtime.h>
#include <cuda_bf16.h>
#include <math.h>

#define DIM   512
#define IDIM  1536
#define BATCH 16
#define TLEN  2048
#define MTOT  (BATCH * TLEN)   // 32768

// ---------------- scratch (static __device__, no allocations) ----------------
__device__ float g_y[(size_t)MTOT * DIM];        // [b,t,c]  64 MB  (post conv+LN)
__device__ float g_h[(size_t)MTOT * IDIM];       // [b,t,i] 201 MB  (post GEMM1+GELU)
__device__ float g_part[8 * BATCH * IDIM];       // GRN partial sums of squares
__device__ float g_scale[BATCH * IDIM];          // GRN per-(b,i) multiplicative scale

// =============================================================================
// Kernel 1: depthwise conv1d (K=7, same pad) + bias, then LayerNorm over C.
// One block handles (b, 16 consecutive t). Output g_y in [b,t,c] layout.
// =============================================================================
__global__ __launch_bounds__(256) void convln_kernel(
    const float* __restrict__ x, const float* __restrict__ dw_w,
    const float* __restrict__ dw_b, const float* __restrict__ ln_g,
    const float* __restrict__ ln_b)
{
    __shared__ float s[DIM][17];   // [c][t_local], pad to 17 (conflict-free col reads)
    const int b  = blockIdx.y;
    const int t0 = blockIdx.x * 16;
    const int tid = threadIdx.x;

    // phase 1: depthwise conv into smem
    for (int idx = tid; idx < DIM * 16; idx += 256) {
        const int c  = idx >> 4;
        const int tl = idx & 15;
        const int t  = t0 + tl;
        const float* xr = x + ((size_t)b * DIM + c) * TLEN;
        const float* wc = dw_w + c * 7;
        float acc = dw_b[c];
        #pragma unroll
        for (int k = 0; k < 7; k++) {
            const int tt = t + k - 3;
            if (tt >= 0 && tt < TLEN) acc += xr[tt] * wc[k];
        }
        s[c][tl] = acc;
    }
    __syncthreads();

    // phase 2: LayerNorm over C per t row (warp per row; 8 warps x 2 rows)
    const int wid = tid >> 5, lane = tid & 31;
    #pragma unroll
    for (int rr = 0; rr < 2; rr++) {
        const int tl = wid + rr * 8;
        float sum = 0.f, sq = 0.f;
        #pragma unroll
        for (int c = lane; c < DIM; c += 32) {
            const float v = s[c][tl];
            sum += v; sq += v * v;
        }
        #pragma unroll
        for (int o = 16; o; o >>= 1) {
            sum += __shfl_xor_sync(0xffffffffu, sum, o);
            sq  += __shfl_xor_sync(0xffffffffu, sq,  o);
        }
        const float mu  = sum * (1.f / DIM);
        const float var = sq * (1.f / DIM) - mu * mu;
        const float rs  = rsqrtf(var + 1e-6f);
        float* yr = g_y + ((size_t)b * TLEN + (t0 + tl)) * DIM;
        for (int c = lane; c < DIM; c += 32)
            yr[c] = (s[c][tl] - mu) * rs * ln_g[c] + ln_b[c];
    }
}

// =============================================================================
// GEMM macro-config: 128x128 tile, BK=16, 256 threads, 8x8 per thread,
// smem double buffered, NT layout (both operands K-major row-major).
// =============================================================================
#define BM 128
#define BN 128
#define BK 16

__device__ __forceinline__ float gelu_exact(float v) {
    return 0.5f * v * (1.0f + erff(v * 0.70710678118654752f));
}

// ---------------- GEMM1: h = gelu(y @ w1^T + b1) -----------------------------
__global__ __launch_bounds__(256) void gemm1_kernel(
    const float* __restrict__ w1, const float* __restrict__ b1)
{
    __shared__ float As[2][BK][BM + 4];
    __shared__ float Bs[2][BK][BN + 4];
    const int tid = threadIdx.x;
    const int m0 = blockIdx.x * BM;
    const int n0 = blockIdx.y * BN;
    const int K = DIM;

    const int lk = (tid & 3) * 4;   // k offset within tile: 0,4,8,12
    const int lr = tid >> 2;        // row 0..63 (and +64)
    const float* Ag = g_y + (size_t)(m0 + lr) * K + lk;
    const float* Bg = w1  + (size_t)(n0 + lr) * K + lk;

    float4 ra0 = *(const float4*)(Ag);
    float4 ra1 = *(const float4*)(Ag + (size_t)64 * K);
    float4 rb0 = *(const float4*)(Bg);
    float4 rb1 = *(const float4*)(Bg + (size_t)64 * K);
    #pragma unroll
    for (int j = 0; j < 4; j++) {
        As[0][lk + j][lr]      = ((float*)&ra0)[j];
        As[0][lk + j][lr + 64] = ((float*)&ra1)[j];
        Bs[0][lk + j][lr]      = ((float*)&rb0)[j];
        Bs[0][lk + j][lr + 64] = ((float*)&rb1)[j];
    }
    __syncthreads();

    float acc[8][8] = {};
    const int tx = tid & 15, ty = tid >> 4;
    const int tm = ty * 8, tn = tx * 8;
    const int NKT = K / BK;
    int st = 0;

    for (int kt = 0; kt < NKT; kt++) {
        if (kt + 1 < NKT) {
            const float* Ag2 = Ag + (kt + 1) * BK;
            const float* Bg2 = Bg + (kt + 1) * BK;
            ra0 = *(const float4*)(Ag2);
            ra1 = *(const float4*)(Ag2 + (size_t)64 * K);
            rb0 = *(const float4*)(Bg2);
            rb1 = *(const float4*)(Bg2 + (size_t)64 * K);
        }
        #pragma unroll
        for (int k = 0; k < BK; k++) {
            float a[8], bb[8];
            *(float4*)&a[0]  = *(const float4*)&As[st][k][tm];
            *(float4*)&a[4]  = *(const float4*)&As[st][k][tm + 4];
            *(float4*)&bb[0] = *(const float4*)&Bs[st][k][tn];
            *(float4*)&bb[4] = *(const float4*)&Bs[st][k][tn + 4];
            #pragma unroll
            for (int i = 0; i < 8; i++)
                #pragma unroll
                for (int j = 0; j < 8; j++)
                    acc[i][j] += a[i] * bb[j];
        }
        if (kt + 1 < NKT) {
            const int s2 = st ^ 1;
            #pragma unroll
            for (int j = 0; j < 4; j++) {
                As[s2][lk + j][lr]      = ((float*)&ra0)[j];
                As[s2][lk + j][lr + 64] = ((float*)&ra1)[j];
                Bs[s2][lk + j][lr]      = ((float*)&rb0)[j];
                Bs[s2][lk + j][lr + 64] = ((float*)&rb1)[j];
            }
            __syncthreads();
            st = s2;
        }
    }

    // epilogue: + b1, exact GELU, store to g_h (coalesced float4)
    float bv[8];
    #pragma unroll
    for (int j = 0; j < 8; j++) bv[j] = b1[n0 + tn + j];
    #pragma unroll
    for (int i = 0; i < 8; i++) {
        float* Hrow = g_h + (size_t)(m0 + tm + i) * IDIM + n0 + tn;
        float o[8];
        #pragma unroll
        for (int j = 0; j < 8; j++) o[j] = gelu_exact(acc[i][j] + bv[j]);
        *(float4*)(Hrow)     = *(float4*)&o[0];
        *(float4*)(Hrow + 4) = *(float4*)&o[4];
    }
}

// ---------------- GRN: partial sum of squares over t -------------------------
__global__ __launch_bounds__(256) void grn_partial_kernel()
{
    const int b  = blockIdx.y;
    const int i  = blockIdx.x * 256 + threadIdx.x;
    const int ch = blockIdx.z;             // 8 chunks of 256 t
    const float* p = g_h + ((size_t)b * TLEN + ch * 256) * IDIM + i;
    float s = 0.f;
    #pragma unroll 8
    for (int t = 0; t < 256; t++) {
        const float v = p[(size_t)t * IDIM];
        s += v * v;
    }
    g_part[((size_t)ch * BATCH + b) * IDIM + i] = s;
}

// ---------------- GRN: mean over channels -> per-(b,i) scale -----------------
__global__ __launch_bounds__(256) void grn_scale_kernel(const float* __restrict__ grn_g)
{
    __shared__ float sgx[IDIM];
    __shared__ float red[256];
    const int b = blockIdx.x;
    const int tid = threadIdx.x;
    float local = 0.f;
    for (int i = tid; i < IDIM; i += 256) {
        float s = 0.f;
        #pragma unroll
        for (int ch = 0; ch < 8; ch++)
            s += g_part[((size_t)ch * BATCH + b) * IDIM + i];
        const float gx = sqrtf(s);
        sgx[i] = gx;
        local += gx;
    }
    red[tid] = local;
    __syncthreads();
    for (int o = 128; o; o >>= 1) {
        if (tid < o) red[tid] += red[tid + o];
        __syncthreads();
    }
    const float mean = red[0] * (1.f / IDIM);
    const float inv  = 1.f / (mean + 1e-6f);
    for (int i = tid; i < IDIM; i += 256)
        g_scale[b * IDIM + i] = grn_g[i] * sgx[i] * inv + 1.0f;
}

// ---------------- GEMM2: out = x + transpose((h*scale+grn_b) @ w2^T + b2) ----
__global__ __launch_bounds__(256) void gemm2_kernel(
    const float* __restrict__ w2, const float* __restrict__ b2,
    const float* __restrict__ grn_b, const float* __restrict__ xres,
    float* __restrict__ out)
{
    __shared__ float As[2][BK][BM + 4];
    __shared__ float Bs[2][BK][BN + 4];
    const int tid = threadIdx.x;
    const int m0 = blockIdx.x * BM;
    const int n0 = blockIdx.y * BN;
    const int K = IDIM;
    const int b  = m0 >> 11;       // 2048 rows per batch, 128 | 2048
    const int t0 = m0 & (TLEN - 1);

    const int lk = (tid & 3) * 4;
    const int lr = tid >> 2;
    const float* Ag = g_h + (size_t)(m0 + lr) * K + lk;
    const float* Bg = w2  + (size_t)(n0 + lr) * K + lk;
    const float* Sc = g_scale + (size_t)b * IDIM;

    float4 ra0, ra1, rb0, rb1, s4, gb4;
    // prologue (k=0)
    ra0 = *(const float4*)(Ag);
    ra1 = *(const float4*)(Ag + (size_t)64 * K);
    rb0 = *(const float4*)(Bg);
    rb1 = *(const float4*)(Bg + (size_t)64 * K);
    s4  = *(const float4*)(Sc + lk);
    gb4 = *(const float4*)(grn_b + lk);
    #pragma unroll
    for (int j = 0; j < 4; j++) {
        const float sj = ((float*)&s4)[j], gj = ((float*)&gb4)[j];
        As[0][lk + j][lr]      = ((float*)&ra0)[j] * sj + gj;
        As[0][lk + j][lr + 64] = ((float*)&ra1)[j] * sj + gj;
        Bs[0][lk + j][lr]      = ((float*)&rb0)[j];
        Bs[0][lk + j][lr + 64] = ((float*)&rb1)[j];
    }
    __syncthreads();

    float acc[8][8] = {};
    const int tx = tid & 15, ty = tid >> 4;
    const int tm = ty * 8, tn = tx * 8;
    const int NKT = K / BK;
    int st = 0;

    for (int kt = 0; kt < NKT; kt++) {
        if (kt + 1 < NKT) {
            const int kn = (kt + 1) * BK;
            ra0 = *(const float4*)(Ag + kn);
            ra1 = *(const float4*)(Ag + kn + (size_t)64 * K);
            rb0 = *(const float4*)(Bg + kn);
            rb1 = *(const float4*)(Bg + kn + (size_t)64 * K);
            s4  = *(const float4*)(Sc + kn + lk);
            gb4 = *(const float4*)(grn_b + kn + lk);
        }
        #pragma unroll
        for (int k = 0; k < BK; k++) {
            float a[8], bb[8];
            *(float4*)&a[0]  = *(const float4*)&As[st][k][tm];
            *(float4*)&a[4]  = *(const float4*)&As[st][k][tm + 4];
            *(float4*)&bb[0] = *(const float4*)&Bs[st][k][tn];
            *(float4*)&bb[4] = *(const float4*)&Bs[st][k][tn + 4];
            #pragma unroll
            for (int i = 0; i < 8; i++)
                #pragma unroll
                for (int j = 0; j < 8; j++)
                    acc[i][j] += a[i] * bb[j];
        }
        if (kt + 1 < NKT) {
            const int s2 = st ^ 1;
            #pragma unroll
            for (int j = 0; j < 4; j++) {
                const float sj = ((float*)&s4)[j], gj = ((float*)&gb4)[j];
                As[s2][lk + j][lr]      = ((float*)&ra0)[j] * sj + gj;
                As[s2][lk + j][lr + 64] = ((float*)&ra1)[j] * sj + gj;
                Bs[s2][lk + j][lr]      = ((float*)&rb0)[j];
                Bs[s2][lk + j][lr + 64] = ((float*)&rb1)[j];
            }
            __syncthreads();
            st = s2;
        }
    }

    // epilogue: transpose via smem (alias As: 32x132 floats = sizeof(As)),
    // add b2 + residual x, coalesced stores along t to out[b,c,t].
    __syncthreads();
    float (*trans)[BM + 4] = (float(*)[BM + 4])(&As[0][0][0]);

    #pragma unroll
    for (int q = 0; q < 4; q++) {         // 32 columns (c) per chunk
        if ((tx >> 2) == q) {
            #pragma unroll
            for (int j = 0; j < 8; j++) {
                const int cl = tn - 32 * q + j;
                #pragma unroll
                for (int i = 0; i < 8; i++)
                    trans[cl][tm + i] = acc[i][j];
            }
        }
        __syncthreads();
        for (int r = tid; r < 32 * BM; r += 256) {
            const int cl = r >> 7, tl = r & 127;
            const int c = n0 + 32 * q + cl;
            const int t = t0 + tl;
            const size_t oi = ((size_t)b * DIM + c) * TLEN + t;
            out[oi] = xres[oi] + trans[cl][tl] + b2[c];
        }
        __syncthreads();
    }
}

// =============================================================================
// Launch
// =============================================================================
extern "C" void kernel_launch(void* const* d_in, const int* in_sizes, int n_in,
                              void* d_out, int out_size)
{
    const float* x     = (const float*)d_in[0];
    const float* dw_w  = (const float*)d_in[1];
    const float* dw_b  = (const float*)d_in[2];
    const float* ln_g  = (const float*)d_in[3];
    const float* ln_b  = (const float*)d_in[4];
    const float* w1    = (const float*)d_in[5];
    const float* b1    = (const float*)d_in[6];
    const float* grn_g = (const float*)d_in[7];
    const float* grn_b = (const float*)d_in[8];
    const float* w2    = (const float*)d_in[9];
    const float* b2    = (const float*)d_in[10];
    float* out = (float*)d_out;

    convln_kernel<<<dim3(TLEN / 16, BATCH), 256>>>(x, dw_w, dw_b, ln_g, ln_b);
    gemm1_kernel<<<dim3(MTOT / BM, IDIM / BN), 256>>>(w1, b1);
    grn_partial_kernel<<<dim3(IDIM / 256, BATCH, 8), 256>>>();
    grn_scale_kernel<<<BATCH, 256>>>(grn_g);
    gemm2_kernel<<<dim3(MTOT / BM, DIM / BN), 256>>>(w2, b2, grn_b, x, out);
}

// round 3
// speedup vs baseline: 2.4345x; 2.4345x over previous
#include <cuda_runtime.h>
#include <math.h>
#include <stdint.h>

#define DIM   512
#define IDIM  1536
#define BATCH 16
#define TLEN  2048
#define MTOT  (BATCH * TLEN)   // 32768

// ---------------- scratch (static __device__, no allocations) ----------------
__device__ float g_y[(size_t)MTOT * DIM];        // [b,t,c]  post conv+LN
__device__ float g_h[(size_t)MTOT * IDIM];       // [b,t,i]  post GEMM1+GELU
__device__ float g_part[8 * BATCH * IDIM];       // GRN partial sums of squares
__device__ float g_scale[BATCH * IDIM];          // GRN multiplicative scale

__device__ __forceinline__ float gelu_exact(float v) {
    return 0.5f * v * (1.0f + erff(v * 0.70710678118654752f));
}
__device__ __forceinline__ uint32_t f2tf32(float f) {
    uint32_t o;
    asm("cvt.rna.tf32.f32 %0, %1;" : "=r"(o) : "f"(f));
    return o;
}
__device__ __forceinline__ void mma_tf32_16n8k8(float* c, const uint32_t* a, const uint32_t* b) {
    asm volatile(
        "mma.sync.aligned.m16n8k8.row.col.f32.tf32.tf32.f32 "
        "{%0,%1,%2,%3}, {%4,%5,%6,%7}, {%8,%9}, {%0,%1,%2,%3};"
        : "+f"(c[0]), "+f"(c[1]), "+f"(c[2]), "+f"(c[3])
        : "r"(a[0]), "r"(a[1]), "r"(a[2]), "r"(a[3]), "r"(b[0]), "r"(b[1]));
}

// =============================================================================
// Kernel 1: depthwise conv1d (K=7, same pad) + bias, then LayerNorm over C.
// =============================================================================
__global__ __launch_bounds__(256) void convln_kernel(
    const float* __restrict__ x, const float* __restrict__ dw_w,
    const float* __restrict__ dw_b, const float* __restrict__ ln_g,
    const float* __restrict__ ln_b)
{
    __shared__ float s[DIM][17];
    const int b  = blockIdx.y;
    const int t0 = blockIdx.x * 16;
    const int tid = threadIdx.x;

    for (int idx = tid; idx < DIM * 16; idx += 256) {
        const int c  = idx >> 4;
        const int tl = idx & 15;
        const int t  = t0 + tl;
        const float* xr = x + ((size_t)b * DIM + c) * TLEN;
        const float* wc = dw_w + c * 7;
        float acc = dw_b[c];
        #pragma unroll
        for (int k = 0; k < 7; k++) {
            const int tt = t + k - 3;
            if (tt >= 0 && tt < TLEN) acc += xr[tt] * wc[k];
        }
        s[c][tl] = acc;
    }
    __syncthreads();

    const int wid = tid >> 5, lane = tid & 31;
    #pragma unroll
    for (int rr = 0; rr < 2; rr++) {
        const int tl = wid + rr * 8;
        float sum = 0.f, sq = 0.f;
        #pragma unroll
        for (int c = lane; c < DIM; c += 32) {
            const float v = s[c][tl];
            sum += v; sq += v * v;
        }
        #pragma unroll
        for (int o = 16; o; o >>= 1) {
            sum += __shfl_xor_sync(0xffffffffu, sum, o);
            sq  += __shfl_xor_sync(0xffffffffu, sq,  o);
        }
        const float mu  = sum * (1.f / DIM);
        const float var = sq * (1.f / DIM) - mu * mu;
        const float rs  = rsqrtf(var + 1e-6f);
        float* yr = g_y + ((size_t)b * TLEN + (t0 + tl)) * DIM;
        for (int c = lane; c < DIM; c += 32)
            yr[c] = (s[c][tl] - mu) * rs * ln_g[c] + ln_b[c];
    }
}

// =============================================================================
// tf32 mma.sync GEMM config: 128x128 tile, BK=16, 256 threads (8 warps, 4m x 2n)
// each warp: 32(m) x 64(n) = 2 x 8 tiles of m16n8k8. smem double buffered,
// register prefetch, 1 sync per K-iter. smem rows padded to 20 floats.
// =============================================================================
#define BK 16
#define SROW 20   // padded floats per smem row

struct SmemGemm {
    uint32_t A[2][128][SROW];
    uint32_t B[2][128][SROW];
};

// compute one BK-slab from smem buffer buf into acc
__device__ __forceinline__ void gemm_compute_slab(
    const SmemGemm* sm, int buf, int wm, int wn, int lane, float acc[2][8][4])
{
    const int r4 = lane >> 2, c4 = lane & 3;
    #pragma unroll
    for (int ks = 0; ks < 2; ks++) {
        const int k0 = ks * 8;
        uint32_t af[2][4], bf[8][2];
        #pragma unroll
        for (int mi = 0; mi < 2; mi++) {
            const int rb = wm * 32 + mi * 16;
            af[mi][0] = sm->A[buf][rb + r4][k0 + c4];
            af[mi][1] = sm->A[buf][rb + r4 + 8][k0 + c4];
            af[mi][2] = sm->A[buf][rb + r4][k0 + c4 + 4];
            af[mi][3] = sm->A[buf][rb + r4 + 8][k0 + c4 + 4];
        }
        #pragma unroll
        for (int j = 0; j < 8; j++) {
            const int nb = wn * 64 + j * 8 + r4;
            bf[j][0] = sm->B[buf][nb][k0 + c4];
            bf[j][1] = sm->B[buf][nb][k0 + c4 + 4];
        }
        #pragma unroll
        for (int mi = 0; mi < 2; mi++)
            #pragma unroll
            for (int j = 0; j < 8; j++)
                mma_tf32_16n8k8(acc[mi][j], af[mi], bf[j]);
    }
}

__device__ __forceinline__ void sts_tf32x4(uint32_t* dst, float4 v) {
    dst[0] = f2tf32(v.x); dst[1] = f2tf32(v.y);
    dst[2] = f2tf32(v.z); dst[3] = f2tf32(v.w);
}

// =============================================================================
// GEMM1: h = gelu(y @ w1^T + b1)   [32768x512] x [1536x512]^T
// =============================================================================
__global__ __launch_bounds__(256) void gemm1_kernel(
    const float* __restrict__ w1, const float* __restrict__ b1)
{
    __shared__ SmemGemm sm;
    const int tid = threadIdx.x;
    const int warp = tid >> 5, lane = tid & 31;
    const int wm = warp & 3, wn = warp >> 2;
    const int n0 = blockIdx.x * 128;
    const int m0 = blockIdx.y * 128;
    const int K = DIM;

    const int lrow = tid >> 2;        // 0..63 (and +64)
    const int lkq  = tid & 3;         // float4 index within BK

    const float* Ag = g_y + (size_t)(m0 + lrow) * K + lkq * 4;
    const float* Bg = w1  + (size_t)(n0 + lrow) * K + lkq * 4;

    float4 pa0 = *(const float4*)(Ag);
    float4 pa1 = *(const float4*)(Ag + (size_t)64 * K);
    float4 pb0 = *(const float4*)(Bg);
    float4 pb1 = *(const float4*)(Bg + (size_t)64 * K);
    sts_tf32x4(&sm.A[0][lrow][lkq * 4], pa0);
    sts_tf32x4(&sm.A[0][lrow + 64][lkq * 4], pa1);
    sts_tf32x4(&sm.B[0][lrow][lkq * 4], pb0);
    sts_tf32x4(&sm.B[0][lrow + 64][lkq * 4], pb1);
    __syncthreads();

    float acc[2][8][4] = {};
    const int NKT = K / BK;
    int buf = 0;
    for (int kt = 0; kt < NKT; kt++) {
        if (kt + 1 < NKT) {
            const int ko = (kt + 1) * BK;
            pa0 = *(const float4*)(Ag + ko);
            pa1 = *(const float4*)(Ag + ko + (size_t)64 * K);
            pb0 = *(const float4*)(Bg + ko);
            pb1 = *(const float4*)(Bg + ko + (size_t)64 * K);
        }
        gemm_compute_slab(&sm, buf, wm, wn, lane, acc);
        if (kt + 1 < NKT) {
            const int b2f = buf ^ 1;
            sts_tf32x4(&sm.A[b2f][lrow][lkq * 4], pa0);
            sts_tf32x4(&sm.A[b2f][lrow + 64][lkq * 4], pa1);
            sts_tf32x4(&sm.B[b2f][lrow][lkq * 4], pb0);
            sts_tf32x4(&sm.B[b2f][lrow + 64][lkq * 4], pb1);
            __syncthreads();
            buf = b2f;
        }
    }

    // epilogue: + b1, exact GELU -> g_h[m][n]
    const int r4 = lane >> 2, c4 = lane & 3;
    #pragma unroll
    for (int mi = 0; mi < 2; mi++) {
        const int m = m0 + wm * 32 + mi * 16 + r4;
        #pragma unroll
        for (int j = 0; j < 8; j++) {
            const int n = n0 + wn * 64 + j * 8 + c4 * 2;
            const float bv0 = b1[n], bv1 = b1[n + 1];
            float2 o0, o1;
            o0.x = gelu_exact(acc[mi][j][0] + bv0);
            o0.y = gelu_exact(acc[mi][j][1] + bv1);
            o1.x = gelu_exact(acc[mi][j][2] + bv0);
            o1.y = gelu_exact(acc[mi][j][3] + bv1);
            *(float2*)(g_h + (size_t)m * IDIM + n)       = o0;
            *(float2*)(g_h + (size_t)(m + 8) * IDIM + n) = o1;
        }
    }
}

// =============================================================================
// GRN: partial sum of squares over t
// =============================================================================
__global__ __launch_bounds__(256) void grn_partial_kernel()
{
    const int b  = blockIdx.y;
    const int i  = blockIdx.x * 256 + threadIdx.x;
    const int ch = blockIdx.z;
    const float* p = g_h + ((size_t)b * TLEN + ch * 256) * IDIM + i;
    float s = 0.f;
    #pragma unroll 8
    for (int t = 0; t < 256; t++) {
        const float v = p[(size_t)t * IDIM];
        s += v * v;
    }
    g_part[((size_t)ch * BATCH + b) * IDIM + i] = s;
}

// =============================================================================
// GRN: mean over channels -> per-(b,i) scale
// =============================================================================
__global__ __launch_bounds__(256) void grn_scale_kernel(const float* __restrict__ grn_g)
{
    __shared__ float sgx[IDIM];
    __shared__ float red[256];
    const int b = blockIdx.x;
    const int tid = threadIdx.x;
    float local = 0.f;
    for (int i = tid; i < IDIM; i += 256) {
        float s = 0.f;
        #pragma unroll
        for (int ch = 0; ch < 8; ch++)
            s += g_part[((size_t)ch * BATCH + b) * IDIM + i];
        const float gx = sqrtf(s);
        sgx[i] = gx;
        local += gx;
    }
    red[tid] = local;
    __syncthreads();
    for (int o = 128; o; o >>= 1) {
        if (tid < o) red[tid] += red[tid + o];
        __syncthreads();
    }
    const float mean = red[0] * (1.f / IDIM);
    const float inv  = 1.f / (mean + 1e-6f);
    for (int i = tid; i < IDIM; i += 256)
        g_scale[b * IDIM + i] = grn_g[i] * sgx[i] * inv + 1.0f;
}

// =============================================================================
// GEMM2: out = x + T((h*scale + grn_b) @ w2^T + b2)  [32768x1536] x [512x1536]^T
// =============================================================================
__global__ __launch_bounds__(256) void gemm2_kernel(
    const float* __restrict__ w2, const float* __restrict__ b2v,
    const float* __restrict__ grn_b, const float* __restrict__ xres,
    float* __restrict__ out)
{
    __shared__ SmemGemm sm;
    const int tid = threadIdx.x;
    const int warp = tid >> 5, lane = tid & 31;
    const int wm = warp & 3, wn = warp >> 2;
    const int n0 = blockIdx.x * 128;
    const int m0 = blockIdx.y * 128;
    const int bb = m0 >> 11;
    const int t0 = m0 & (TLEN - 1);
    const int K = IDIM;

    const int lrow = tid >> 2;
    const int lkq  = tid & 3;

    const float* Ag = g_h + (size_t)(m0 + lrow) * K + lkq * 4;
    const float* Bg = w2  + (size_t)(n0 + lrow) * K + lkq * 4;
    const float* Sc = g_scale + (size_t)bb * IDIM + lkq * 4;
    const float* Gb = grn_b + lkq * 4;

    float4 pa0, pa1, pb0, pb1, s4, g4;
    pa0 = *(const float4*)(Ag);
    pa1 = *(const float4*)(Ag + (size_t)64 * K);
    pb0 = *(const float4*)(Bg);
    pb1 = *(const float4*)(Bg + (size_t)64 * K);
    s4  = *(const float4*)(Sc);
    g4  = *(const float4*)(Gb);
    {
        float4 a0 = pa0, a1 = pa1;
        a0.x = a0.x * s4.x + g4.x; a0.y = a0.y * s4.y + g4.y;
        a0.z = a0.z * s4.z + g4.z; a0.w = a0.w * s4.w + g4.w;
        a1.x = a1.x * s4.x + g4.x; a1.y = a1.y * s4.y + g4.y;
        a1.z = a1.z * s4.z + g4.z; a1.w = a1.w * s4.w + g4.w;
        sts_tf32x4(&sm.A[0][lrow][lkq * 4], a0);
        sts_tf32x4(&sm.A[0][lrow + 64][lkq * 4], a1);
        sts_tf32x4(&sm.B[0][lrow][lkq * 4], pb0);
        sts_tf32x4(&sm.B[0][lrow + 64][lkq * 4], pb1);
    }
    __syncthreads();

    float acc[2][8][4] = {};
    const int NKT = K / BK;
    int buf = 0;
    for (int kt = 0; kt < NKT; kt++) {
        if (kt + 1 < NKT) {
            const int ko = (kt + 1) * BK;
            pa0 = *(const float4*)(Ag + ko);
            pa1 = *(const float4*)(Ag + ko + (size_t)64 * K);
            pb0 = *(const float4*)(Bg + ko);
            pb1 = *(const float4*)(Bg + ko + (size_t)64 * K);
            s4  = *(const float4*)(Sc + ko);
            g4  = *(const float4*)(Gb + ko);
        }
        gemm_compute_slab(&sm, buf, wm, wn, lane, acc);
        if (kt + 1 < NKT) {
            const int b2f = buf ^ 1;
            float4 a0 = pa0, a1 = pa1;
            a0.x = a0.x * s4.x + g4.x; a0.y = a0.y * s4.y + g4.y;
            a0.z = a0.z * s4.z + g4.z; a0.w = a0.w * s4.w + g4.w;
            a1.x = a1.x * s4.x + g4.x; a1.y = a1.y * s4.y + g4.y;
            a1.z = a1.z * s4.z + g4.z; a1.w = a1.w * s4.w + g4.w;
            sts_tf32x4(&sm.A[b2f][lrow][lkq * 4], a0);
            sts_tf32x4(&sm.A[b2f][lrow + 64][lkq * 4], a1);
            sts_tf32x4(&sm.B[b2f][lrow][lkq * 4], pb0);
            sts_tf32x4(&sm.B[b2f][lrow + 64][lkq * 4], pb1);
            __syncthreads();
            buf = b2f;
        }
    }
    __syncthreads();   // all compute done; smem now reusable for transpose

    // epilogue: transpose via smem (alias sm), 4 chunks of 32 n-cols.
    float (*trans)[132] = (float(*)[132]) & sm;   // [32][132] = 16.9 KB
    const int r4 = lane >> 2, c4 = lane & 3;

    #pragma unroll
    for (int q = 0; q < 4; q++) {
        if (wn == (q >> 1)) {
            const int jb = (q & 1) * 4;
            #pragma unroll
            for (int jl = 0; jl < 4; jl++) {
                const int cl = (jb + jl) * 8 + c4 * 2 - (q & 1) * 32;  // 0..31
                #pragma unroll
                for (int mi = 0; mi < 2; mi++) {
                    const int ml = wm * 32 + mi * 16 + r4;
                    trans[cl][ml]         = acc[mi][jb + jl][0];
                    trans[cl + 1][ml]     = acc[mi][jb + jl][1];
                    trans[cl][ml + 8]     = acc[mi][jb + jl][2];
                    trans[cl + 1][ml + 8] = acc[mi][jb + jl][3];
                }
            }
        }
        __syncthreads();
        for (int r = tid; r < 32 * 128; r += 256) {
            const int cl = r >> 7, tl = r & 127;
            const int c = n0 + 32 * q + cl;
            const size_t oi = ((size_t)(bb * DIM + c)) * TLEN + t0 + tl;
            out[oi] = xres[oi] + trans[cl][tl] + b2v[c];
        }
        __syncthreads();
    }
}

// =============================================================================
// Launch
// =============================================================================
extern "C" void kernel_launch(void* const* d_in, const int* in_sizes, int n_in,
                              void* d_out, int out_size)
{
    const float* x     = (const float*)d_in[0];
    const float* dw_w  = (const float*)d_in[1];
    const float* dw_b  = (const float*)d_in[2];
    const float* ln_g  = (const float*)d_in[3];
    const float* ln_b  = (const float*)d_in[4];
    const float* w1    = (const float*)d_in[5];
    const float* b1    = (const float*)d_in[6];
    const float* grn_g = (const float*)d_in[7];
    const float* grn_b = (const float*)d_in[8];
    const float* w2    = (const float*)d_in[9];
    const float* b2    = (const float*)d_in[10];
    float* out = (float*)d_out;

    convln_kernel<<<dim3(TLEN / 16, BATCH), 256>>>(x, dw_w, dw_b, ln_g, ln_b);
    gemm1_kernel<<<dim3(IDIM / 128, MTOT / 128), 256>>>(w1, b1);
    grn_partial_kernel<<<dim3(IDIM / 256, BATCH, 8), 256>>>();
    grn_scale_kernel<<<BATCH, 256>>>(grn_g);
    gemm2_kernel<<<dim3(DIM / 128, MTOT / 128), 256>>>(w2, b2, grn_b, x, out);
}

// round 4
// speedup vs baseline: 3.0480x; 1.2520x over previous
#include <cuda_runtime.h>
#include <math.h>
#include <stdint.h>

#define DIM   512
#define IDIM  1536
#define BATCH 16
#define TLEN  2048
#define MTOT  (BATCH * TLEN)   // 32768

#define STAGES      4
#define STAGE_BYTES 16384      // A tile 8KB + B tile 8KB per stage

// ---------------- scratch (static __device__, no allocations) ----------------
__device__ float g_y[(size_t)MTOT * DIM];        // [b,t,c] tf32-rounded conv+LN
__device__ float g_h[(size_t)MTOT * IDIM];       // [b,t,i] tf32-rounded gelu out
__device__ float g_w1t[(size_t)IDIM * DIM];      // tf32-rounded w1
__device__ float g_w2t[(size_t)DIM * IDIM];      // tf32-rounded w2
__device__ float g_part[BATCH * IDIM];           // GRN sum of squares (atomics)
__device__ float g_scale[BATCH * IDIM];          // GRN multiplicative scale
__device__ float g_gw2[DIM];                     // grn_b @ w2^T

// =============================================================================
// small helpers
// =============================================================================
__device__ __forceinline__ float gelu_exact(float v) {
    return 0.5f * v * (1.0f + erff(v * 0.70710678118654752f));
}
__device__ __forceinline__ uint32_t f2tf32(float f) {
    uint32_t o;
    asm("cvt.rna.tf32.f32 %0, %1;" : "=r"(o) : "f"(f));
    return o;
}
__device__ __forceinline__ float round_tf32(float f) {
    return __uint_as_float(f2tf32(f));
}
__device__ __forceinline__ uint32_t smem_u32(const void* p) {
    uint32_t a;
    asm("{ .reg .u64 t; cvta.to.shared.u64 t, %1; cvt.u32.u64 %0, t; }"
        : "=r"(a) : "l"(p));
    return a;
}
__device__ __forceinline__ void cp_async16(uint32_t dst, const void* src) {
    asm volatile("cp.async.ca.shared.global [%0], [%1], 16;" :: "r"(dst), "l"(src));
}
#define CP_COMMIT() asm volatile("cp.async.commit_group;" ::: "memory")
#define CP_WAIT(n)  asm volatile("cp.async.wait_group %0;" :: "n"(n) : "memory")

__device__ __forceinline__ void ldsm_x4(uint32_t* d, uint32_t addr) {
    asm volatile("ldmatrix.sync.aligned.m8n8.x4.shared.b16 {%0,%1,%2,%3}, [%4];"
                 : "=r"(d[0]), "=r"(d[1]), "=r"(d[2]), "=r"(d[3]) : "r"(addr));
}
__device__ __forceinline__ float lds_f32(uint32_t a) {
    float v;
    asm volatile("ld.shared.f32 %0, [%1];" : "=f"(v) : "r"(a));
    return v;
}
__device__ __forceinline__ void mma_tf32_16n8k8(float* c, const uint32_t* a, const uint32_t* b) {
    asm volatile(
        "mma.sync.aligned.m16n8k8.row.col.f32.tf32.tf32.f32 "
        "{%0,%1,%2,%3}, {%4,%5,%6,%7}, {%8,%9}, {%0,%1,%2,%3};"
        : "+f"(c[0]), "+f"(c[1]), "+f"(c[2]), "+f"(c[3])
        : "r"(a[0]), "r"(a[1]), "r"(a[2]), "r"(a[3]), "r"(b[0]), "r"(b[1]));
}

// issue one pipeline stage: 128x16 f32 tiles of A and B into stage st.
// Smem rows are 64B (16 floats = 4 chunks of 16B), chunk XOR-swizzled by (r>>1)&3.
__device__ __forceinline__ void issue_stage(
    uint32_t sb, int st, const float* Ag, const float* Bg, int kt, int tid, int K)
{
    const uint32_t base = sb + st * STAGE_BYTES;
    #pragma unroll
    for (int q = 0; q < 2; q++) {
        const int cid = tid + q * 256;
        const int r = cid >> 2, c = cid & 3;
        const uint32_t so = (uint32_t)(r * 64 + ((c ^ ((r >> 1) & 3)) << 4));
        cp_async16(base + so,        Ag + (size_t)r * K + kt * 16 + c * 4);
        cp_async16(base + 8192 + so, Bg + (size_t)r * K + kt * 16 + c * 4);
    }
}

// one BK=16 compute iteration from stage buffer (abase/bbase), ldmatrix frags.
template<bool SCALE>
__device__ __forceinline__ void compute_kiter(
    uint32_t abase, uint32_t bbase,
    uint32_t offA0, const uint32_t* cswA,
    uint32_t offB0, const uint32_t* cswB,
    uint32_t s_addr,                       // SCALE: smem addr of s[k= kt*16 + c4]
    float acc[2][8][4])
{
    #pragma unroll
    for (int ks = 0; ks < 2; ks++) {
        uint32_t af[2][4];
        ldsm_x4(af[0], abase + offA0 + cswA[ks]);
        ldsm_x4(af[1], abase + offA0 + 1024 + cswA[ks]);
        if (SCALE) {
            const float sv0 = lds_f32(s_addr + ks * 32);
            const float sv1 = lds_f32(s_addr + ks * 32 + 16);
            #pragma unroll
            for (int mi = 0; mi < 2; mi++) {
                af[mi][0] = f2tf32(__uint_as_float(af[mi][0]) * sv0);
                af[mi][1] = f2tf32(__uint_as_float(af[mi][1]) * sv0);
                af[mi][2] = f2tf32(__uint_as_float(af[mi][2]) * sv1);
                af[mi][3] = f2tf32(__uint_as_float(af[mi][3]) * sv1);
            }
        }
        uint32_t bf[4][4];
        #pragma unroll
        for (int q = 0; q < 4; q++)
            ldsm_x4(bf[q], bbase + offB0 + q * 1024 + cswB[ks]);
        #pragma unroll
        for (int mi = 0; mi < 2; mi++)
            #pragma unroll
            for (int j = 0; j < 8; j++)
                mma_tf32_16n8k8(acc[mi][j], af[mi], &bf[j >> 1][(j & 1) * 2]);
    }
}

// =============================================================================
// prep: round w1, w2 to tf32 scratch; zero g_part.
// =============================================================================
__global__ __launch_bounds__(256) void prep_kernel(
    const float* __restrict__ w1, const float* __restrict__ w2)
{
    const int i = blockIdx.x * 256 + threadIdx.x;   // 196608 threads, x4 elements
    {
        float4 v = *(const float4*)(w1 + (size_t)i * 4);
        v.x = round_tf32(v.x); v.y = round_tf32(v.y);
        v.z = round_tf32(v.z); v.w = round_tf32(v.w);
        *(float4*)(g_w1t + (size_t)i * 4) = v;
    }
    {
        float4 v = *(const float4*)(w2 + (size_t)i * 4);
        v.x = round_tf32(v.x); v.y = round_tf32(v.y);
        v.z = round_tf32(v.z); v.w = round_tf32(v.w);
        *(float4*)(g_w2t + (size_t)i * 4) = v;
    }
    if (i < BATCH * IDIM / 4)
        *(float4*)(g_part + (size_t)i * 4) = make_float4(0.f, 0.f, 0.f, 0.f);
}

// =============================================================================
// conv1d depthwise (K=7) + bias + LayerNorm over C; store tf32-rounded.
// =============================================================================
__global__ __launch_bounds__(256) void convln_kernel(
    const float* __restrict__ x, const float* __restrict__ dw_w,
    const float* __restrict__ dw_b, const float* __restrict__ ln_g,
    const float* __restrict__ ln_b)
{
    __shared__ float s[DIM][17];
    const int b  = blockIdx.y;
    const int t0 = blockIdx.x * 16;
    const int tid = threadIdx.x;

    for (int idx = tid; idx < DIM * 16; idx += 256) {
        const int c  = idx >> 4;
        const int tl = idx & 15;
        const int t  = t0 + tl;
        const float* xr = x + ((size_t)b * DIM + c) * TLEN;
        const float* wc = dw_w + c * 7;
        float acc = dw_b[c];
        #pragma unroll
        for (int k = 0; k < 7; k++) {
            const int tt = t + k - 3;
            if (tt >= 0 && tt < TLEN) acc += xr[tt] * wc[k];
        }
        s[c][tl] = acc;
    }
    __syncthreads();

    const int wid = tid >> 5, lane = tid & 31;
    #pragma unroll
    for (int rr = 0; rr < 2; rr++) {
        const int tl = wid + rr * 8;
        float sum = 0.f, sq = 0.f;
        #pragma unroll
        for (int c = lane; c < DIM; c += 32) {
            const float v = s[c][tl];
            sum += v; sq += v * v;
        }
        #pragma unroll
        for (int o = 16; o; o >>= 1) {
            sum += __shfl_xor_sync(0xffffffffu, sum, o);
            sq  += __shfl_xor_sync(0xffffffffu, sq,  o);
        }
        const float mu  = sum * (1.f / DIM);
        const float var = sq * (1.f / DIM) - mu * mu;
        const float rs  = rsqrtf(var + 1e-6f);
        float* yr = g_y + ((size_t)b * TLEN + (t0 + tl)) * DIM;
        for (int c = lane; c < DIM; c += 32)
            yr[c] = round_tf32((s[c][tl] - mu) * rs * ln_g[c] + ln_b[c]);
    }
}

// =============================================================================
// GEMM1: h = gelu(y @ w1t^T + b1); fused GRN sum-of-squares into g_part.
// =============================================================================
__global__ void __launch_bounds__(256, 2) gemm1_kernel(
    const float* __restrict__ b1)
{
    extern __shared__ char smem[];
    const uint32_t sb = smem_u32(smem);
    const int tid = threadIdx.x;
    const int warp = tid >> 5, lane = tid & 31;
    const int wm = warp & 3, wn = warp >> 2;
    const int n0 = blockIdx.x * 128;
    const int m0 = blockIdx.y * 128;
    const int K = DIM, NKT = DIM / 16;

    const float* Ag = g_y   + (size_t)m0 * K;
    const float* Bg = g_w1t + (size_t)n0 * K;

    // fragment ldmatrix lane offsets
    const int t8 = lane >> 3, rloc = lane & 7;
    const int growA0 = wm * 32 + (t8 & 1) * 8 + rloc;
    const uint32_t offA0 = growA0 * 64;
    const uint32_t rmA = (growA0 >> 1) & 3;
    const uint32_t cswA[2] = { (((uint32_t)(t8 >> 1)) ^ rmA) << 4,
                               (((uint32_t)(t8 >> 1) + 2) ^ rmA) << 4 };
    const int growB0 = wn * 64 + (t8 >> 1) * 8 + rloc;
    const uint32_t offB0 = growB0 * 64;
    const uint32_t rmB = (growB0 >> 1) & 3;
    const uint32_t cswB[2] = { (((uint32_t)(t8 & 1)) ^ rmB) << 4,
                               (((uint32_t)(t8 & 1) + 2) ^ rmB) << 4 };

    #pragma unroll
    for (int st = 0; st < STAGES - 1; st++) {
        issue_stage(sb, st, Ag, Bg, st, tid, K);
        CP_COMMIT();
    }

    float acc[2][8][4] = {};
    for (int kt = 0; kt < NKT; kt++) {
        CP_WAIT(STAGES - 2);
        __syncthreads();
        const int pf = kt + STAGES - 1;
        if (pf < NKT) issue_stage(sb, pf % STAGES, Ag, Bg, pf, tid, K);
        CP_COMMIT();
        const uint32_t abase = sb + (kt % STAGES) * STAGE_BYTES;
        compute_kiter<false>(abase, abase + 8192, offA0, cswA, offB0, cswB, 0, acc);
    }
    CP_WAIT(0);

    // epilogue: bias + exact GELU (in place), tf32-round, store, fused sumsq
    const int r4 = lane >> 2, c4 = lane & 3;
    #pragma unroll
    for (int mi = 0; mi < 2; mi++) {
        #pragma unroll
        for (int j = 0; j < 8; j++) {
            const int n = n0 + wn * 64 + j * 8 + c4 * 2;
            const float bv0 = b1[n], bv1 = b1[n + 1];
            acc[mi][j][0] = round_tf32(gelu_exact(acc[mi][j][0] + bv0));
            acc[mi][j][1] = round_tf32(gelu_exact(acc[mi][j][1] + bv1));
            acc[mi][j][2] = round_tf32(gelu_exact(acc[mi][j][2] + bv0));
            acc[mi][j][3] = round_tf32(gelu_exact(acc[mi][j][3] + bv1));
        }
    }
    #pragma unroll
    for (int mi = 0; mi < 2; mi++) {
        const int m = m0 + wm * 32 + mi * 16 + r4;
        #pragma unroll
        for (int j = 0; j < 8; j++) {
            const int n = n0 + wn * 64 + j * 8 + c4 * 2;
            *(float2*)(g_h + (size_t)m * IDIM + n)       = make_float2(acc[mi][j][0], acc[mi][j][1]);
            *(float2*)(g_h + (size_t)(m + 8) * IDIM + n) = make_float2(acc[mi][j][2], acc[mi][j][3]);
        }
    }
    const int b = m0 >> 11;
    #pragma unroll
    for (int j = 0; j < 8; j++) {
        float s0 = acc[0][j][0] * acc[0][j][0] + acc[0][j][2] * acc[0][j][2]
                 + acc[1][j][0] * acc[1][j][0] + acc[1][j][2] * acc[1][j][2];
        float s1 = acc[0][j][1] * acc[0][j][1] + acc[0][j][3] * acc[0][j][3]
                 + acc[1][j][1] * acc[1][j][1] + acc[1][j][3] * acc[1][j][3];
        #pragma unroll
        for (int o = 4; o < 32; o <<= 1) {
            s0 += __shfl_xor_sync(0xffffffffu, s0, o);
            s1 += __shfl_xor_sync(0xffffffffu, s1, o);
        }
        if (lane < 4) {
            const int n = n0 + wn * 64 + j * 8 + lane * 2;
            atomicAdd(&g_part[b * IDIM + n],     s0);
            atomicAdd(&g_part[b * IDIM + n + 1], s1);
        }
    }
}

// =============================================================================
// GRN scale:  scale[b][i] = 1 + grn_g[i] * gx / (mean_i(gx) + 1e-6)
// =============================================================================
__global__ __launch_bounds__(256) void grn_scale_kernel(const float* __restrict__ grn_g)
{
    __shared__ float sgx[IDIM];
    __shared__ float red[256];
    const int b = blockIdx.x;
    const int tid = threadIdx.x;
    float local = 0.f;
    for (int i = tid; i < IDIM; i += 256) {
        const float gx = sqrtf(g_part[b * IDIM + i]);
        sgx[i] = gx;
        local += gx;
    }
    red[tid] = local;
    __syncthreads();
    for (int o = 128; o; o >>= 1) {
        if (tid < o) red[tid] += red[tid + o];
        __syncthreads();
    }
    const float mean = red[0] * (1.f / IDIM);
    const float inv  = 1.f / (mean + 1e-6f);
    for (int i = tid; i < IDIM; i += 256)
        g_scale[b * IDIM + i] = grn_g[i] * sgx[i] * inv + 1.0f;
}

// =============================================================================
// gw2[c] = sum_i grn_b[i] * w2t[c][i]   (one warp per c)
// =============================================================================
__global__ __launch_bounds__(256) void gw2_kernel(const float* __restrict__ grn_b)
{
    const int w = (blockIdx.x * 256 + threadIdx.x) >> 5;   // 0..511
    const int lane = threadIdx.x & 31;
    const float* row = g_w2t + (size_t)w * IDIM;
    float s = 0.f;
    for (int i = lane; i < IDIM; i += 32) s += row[i] * grn_b[i];
    #pragma unroll
    for (int o = 16; o; o >>= 1) s += __shfl_xor_sync(0xffffffffu, s, o);
    if (lane == 0) g_gw2[w] = s;
}

// =============================================================================
// GEMM2: out = x + T( (h*scale) @ w2t^T + gw2 + b2 )
// =============================================================================
__global__ void __launch_bounds__(256, 2) gemm2_kernel(
    const float* __restrict__ b2v, const float* __restrict__ xres,
    float* __restrict__ out)
{
    extern __shared__ char smem[];
    const uint32_t sb = smem_u32(smem);
    const int tid = threadIdx.x;
    const int warp = tid >> 5, lane = tid & 31;
    const int wm = warp & 3, wn = warp >> 2;
    const int n0 = blockIdx.x * 128;
    const int m0 = blockIdx.y * 128;
    const int bb = m0 >> 11;
    const int t0 = m0 & (TLEN - 1);
    const int K = IDIM, NKT = IDIM / 16;

    const float* Ag = g_h   + (size_t)m0 * K;
    const float* Bg = g_w2t + (size_t)n0 * K;

    // load GRN scale row for this batch into smem (after stage buffers)
    const uint32_t s_base = sb + STAGES * STAGE_BYTES;
    {
        const float* Sc = g_scale + (size_t)bb * IDIM;
        for (int i = tid; i < IDIM / 4; i += 256) {
            const float4 v = *(const float4*)(Sc + i * 4);
            *(float4*)(smem + STAGES * STAGE_BYTES + i * 16) = v;
        }
    }

    const int t8 = lane >> 3, rloc = lane & 7;
    const int growA0 = wm * 32 + (t8 & 1) * 8 + rloc;
    const uint32_t offA0 = growA0 * 64;
    const uint32_t rmA = (growA0 >> 1) & 3;
    const uint32_t cswA[2] = { (((uint32_t)(t8 >> 1)) ^ rmA) << 4,
                               (((uint32_t)(t8 >> 1) + 2) ^ rmA) << 4 };
    const int growB0 = wn * 64 + (t8 >> 1) * 8 + rloc;
    const uint32_t offB0 = growB0 * 64;
    const uint32_t rmB = (growB0 >> 1) & 3;
    const uint32_t cswB[2] = { (((uint32_t)(t8 & 1)) ^ rmB) << 4,
                               (((uint32_t)(t8 & 1) + 2) ^ rmB) << 4 };

    #pragma unroll
    for (int st = 0; st < STAGES - 1; st++) {
        issue_stage(sb, st, Ag, Bg, st, tid, K);
        CP_COMMIT();
    }

    float acc[2][8][4] = {};
    for (int kt = 0; kt < NKT; kt++) {
        CP_WAIT(STAGES - 2);
        __syncthreads();
        const int pf = kt + STAGES - 1;
        if (pf < NKT) issue_stage(sb, pf % STAGES, Ag, Bg, pf, tid, K);
        CP_COMMIT();
        const uint32_t abase = sb + (kt % STAGES) * STAGE_BYTES;
        const uint32_t s_addr = s_base + (kt * 16 + (lane & 3)) * 4;
        compute_kiter<true>(abase, abase + 8192, offA0, cswA, offB0, cswB, s_addr, acc);
    }
    CP_WAIT(0);
    __syncthreads();

    // epilogue: transpose via smem (alias stage buffers), residual + biases.
    float (*trans)[132] = (float(*)[132])smem;   // [32][132]
    const int r4 = lane >> 2, c4 = lane & 3;

    #pragma unroll
    for (int q = 0; q < 4; q++) {
        if (wn == (q >> 1)) {
            const int jb = (q & 1) * 4;
            #pragma unroll
            for (int jl = 0; jl < 4; jl++) {
                const int cl = (jb + jl) * 8 + c4 * 2 - (q & 1) * 32;  // 0..31
                #pragma unroll
                for (int mi = 0; mi < 2; mi++) {
                    const int ml = wm * 32 + mi * 16 + r4;
                    trans[cl][ml]         = acc[mi][jb + jl][0];
                    trans[cl + 1][ml]     = acc[mi][jb + jl][1];
                    trans[cl][ml + 8]     = acc[mi][jb + jl][2];
                    trans[cl + 1][ml + 8] = acc[mi][jb + jl][3];
                }
            }
        }
        __syncthreads();
        for (int r = tid; r < 32 * 128; r += 256) {
            const int cl = r >> 7, tl = r & 127;
            const int c = n0 + 32 * q + cl;
            const size_t oi = ((size_t)(bb * DIM + c)) * TLEN + t0 + tl;
            out[oi] = xres[oi] + trans[cl][tl] + b2v[c] + g_gw2[c];
        }
        __syncthreads();
    }
}

// =============================================================================
// Launch
// =============================================================================
extern "C" void kernel_launch(void* const* d_in, const int* in_sizes, int n_in,
                              void* d_out, int out_size)
{
    const float* x     = (const float*)d_in[0];
    const float* dw_w  = (const float*)d_in[1];
    const float* dw_b  = (const float*)d_in[2];
    const float* ln_g  = (const float*)d_in[3];
    const float* ln_b  = (const float*)d_in[4];
    const float* w1    = (const float*)d_in[5];
    const float* b1    = (const float*)d_in[6];
    const float* grn_g = (const float*)d_in[7];
    const float* grn_b = (const float*)d_in[8];
    const float* w2    = (const float*)d_in[9];
    const float* b2    = (const float*)d_in[10];
    float* out = (float*)d_out;

    const int smem1 = STAGES * STAGE_BYTES;                 // 64 KB
    const int smem2 = STAGES * STAGE_BYTES + IDIM * 4;      // 64 KB + 6 KB
    cudaFuncSetAttribute(gemm1_kernel, cudaFuncAttributeMaxDynamicSharedMemorySize, smem1);
    cudaFuncSetAttribute(gemm2_kernel, cudaFuncAttributeMaxDynamicSharedMemorySize, smem2);

    prep_kernel<<<768, 256>>>(w1, w2);
    convln_kernel<<<dim3(TLEN / 16, BATCH), 256>>>(x, dw_w, dw_b, ln_g, ln_b);
    gemm1_kernel<<<dim3(IDIM / 128, MTOT / 128), 256, smem1>>>(b1);
    grn_scale_kernel<<<BATCH, 256>>>(grn_g);
    gw2_kernel<<<64, 256>>>(grn_b);
    gemm2_kernel<<<dim3(DIM / 128, MTOT / 128), 256, smem2>>>(b2, x, out);
}

// round 5
// speedup vs baseline: 4.6216x; 1.5163x over previous
#include <cuda_runtime.h>
#include <cuda_fp16.h>
#include <math.h>
#include <stdint.h>

#define DIM   512
#define IDIM  1536
#define BATCH 16
#define TLEN  2048
#define MTOT  (BATCH * TLEN)   // 32768

#define STAGES      4
#define STAGE_BYTES 16384      // A tile 8KB + B tile 8KB (128 x 32 halves each)
#define BK          32

// ---------------- scratch (static __device__, no allocations) ----------------
__device__ __half g_y[(size_t)MTOT * DIM];       // [b,t,c] half conv+LN out
__device__ __half g_h[(size_t)MTOT * IDIM];      // [b,t,i] half gelu out
__device__ __half g_w1h[(size_t)IDIM * DIM];     // half w1
__device__ __half g_w2h[(size_t)DIM * IDIM];     // half w2
__device__ float  g_part[BATCH * IDIM];          // GRN sum of squares (atomics)
__device__ __half g_scale[BATCH * IDIM];         // GRN multiplicative scale
__device__ float  g_gw2[DIM];                    // grn_b @ w2^T

// =============================================================================
// helpers
// =============================================================================
__device__ __forceinline__ float gelu_exact(float v) {
    return 0.5f * v * (1.0f + erff(v * 0.70710678118654752f));
}
__device__ __forceinline__ uint32_t smem_u32(const void* p) {
    uint32_t a;
    asm("{ .reg .u64 t; cvta.to.shared.u64 t, %1; cvt.u32.u64 %0, t; }"
        : "=r"(a) : "l"(p));
    return a;
}
__device__ __forceinline__ void cp_async16(uint32_t dst, const void* src) {
    asm volatile("cp.async.ca.shared.global [%0], [%1], 16;" :: "r"(dst), "l"(src));
}
#define CP_COMMIT() asm volatile("cp.async.commit_group;" ::: "memory")
#define CP_WAIT(n)  asm volatile("cp.async.wait_group %0;" :: "n"(n) : "memory")

__device__ __forceinline__ void ldsm_x4(uint32_t* d, uint32_t addr) {
    asm volatile("ldmatrix.sync.aligned.m8n8.x4.shared.b16 {%0,%1,%2,%3}, [%4];"
                 : "=r"(d[0]), "=r"(d[1]), "=r"(d[2]), "=r"(d[3]) : "r"(addr));
}
__device__ __forceinline__ uint32_t lds_u32(uint32_t a) {
    uint32_t v;
    asm volatile("ld.shared.b32 %0, [%1];" : "=r"(v) : "r"(a));
    return v;
}
__device__ __forceinline__ uint32_t hmul2(uint32_t a, uint32_t s) {
    uint32_t o;
    asm("mul.rn.f16x2 %0, %1, %2;" : "=r"(o) : "r"(a), "r"(s));
    return o;
}
__device__ __forceinline__ void mma_f16(float* c, const uint32_t* a, const uint32_t* b) {
    asm volatile(
        "mma.sync.aligned.m16n8k16.row.col.f32.f16.f16.f32 "
        "{%0,%1,%2,%3}, {%4,%5,%6,%7}, {%8,%9}, {%0,%1,%2,%3};"
        : "+f"(c[0]), "+f"(c[1]), "+f"(c[2]), "+f"(c[3])
        : "r"(a[0]), "r"(a[1]), "r"(a[2]), "r"(a[3]), "r"(b[0]), "r"(b[1]));
}

// issue one stage: 128x32-half tiles of A and B. Rows are 64B = 4 chunks of 16B,
// chunk XOR-swizzled by (row>>1)&3.
__device__ __forceinline__ void issue_stage(
    uint32_t sb, int st, const __half* Ag, const __half* Bg, int kt, int tid, int K)
{
    const uint32_t base = sb + st * STAGE_BYTES;
    #pragma unroll
    for (int q = 0; q < 2; q++) {
        const int cid = tid + q * 256;          // 0..511
        const int r = cid >> 2, c = cid & 3;
        const uint32_t so = (uint32_t)(r * 64 + ((c ^ ((r >> 1) & 3)) << 4));
        cp_async16(base + so,        Ag + (size_t)r * K + kt * BK + c * 8);
        cp_async16(base + 8192 + so, Bg + (size_t)r * K + kt * BK + c * 8);
    }
}

// one BK=32 compute iteration (two k16 steps)
template<bool SCALE>
__device__ __forceinline__ void compute_kiter(
    uint32_t abase, uint32_t bbase,
    uint32_t offA0, const uint32_t* cswA,
    uint32_t offB0, const uint32_t* cswB,
    uint32_t s_addr,                       // SCALE: smem byte addr of scale[k pair]
    float acc[2][8][4])
{
    #pragma unroll
    for (int ks = 0; ks < 2; ks++) {
        uint32_t af[2][4];
        ldsm_x4(af[0], abase + offA0 + cswA[ks]);
        ldsm_x4(af[1], abase + offA0 + 1024 + cswA[ks]);
        if (SCALE) {
            const uint32_t slo = lds_u32(s_addr + ks * 32);
            const uint32_t shi = lds_u32(s_addr + ks * 32 + 16);
            #pragma unroll
            for (int mi = 0; mi < 2; mi++) {
                af[mi][0] = hmul2(af[mi][0], slo);
                af[mi][1] = hmul2(af[mi][1], slo);
                af[mi][2] = hmul2(af[mi][2], shi);
                af[mi][3] = hmul2(af[mi][3], shi);
            }
        }
        uint32_t bf[4][4];
        #pragma unroll
        for (int q = 0; q < 4; q++)
            ldsm_x4(bf[q], bbase + offB0 + q * 1024 + cswB[ks]);
        #pragma unroll
        for (int mi = 0; mi < 2; mi++)
            #pragma unroll
            for (int j = 0; j < 8; j++)
                mma_f16(acc[mi][j], af[mi], &bf[j >> 1][(j & 1) * 2]);
    }
}

// fragment address setup (per-lane constants)
struct FragAddr {
    uint32_t offA0, offB0;
    uint32_t cswA[2], cswB[2];
};
__device__ __forceinline__ FragAddr make_frag_addr(int warp, int lane) {
    FragAddr fa;
    const int wm = warp & 3, wn = warp >> 2;
    const int mi4 = lane >> 3, rloc = lane & 7;
    // A x4: matrices (rows +0/+8) x (chunk lo/hi): rowA = mb + (mi4&1)*8 + rloc
    const int rowA = wm * 32 + (mi4 & 1) * 8 + rloc;
    fa.offA0 = rowA * 64;
    const uint32_t rmA = (rowA >> 1) & 3;
    const uint32_t chA = (uint32_t)(mi4 >> 1);       // 0 lo / 1 hi 16B
    fa.cswA[0] = ((0 + chA) ^ rmA) << 4;
    fa.cswA[1] = ((2 + chA) ^ rmA) << 4;
    // B x4: matrices (rows +0/+8 chosen by mi4>>1) x (chunk by mi4&1)
    const int rowB = wn * 64 + (mi4 >> 1) * 8 + rloc;
    fa.offB0 = rowB * 64;
    const uint32_t rmB = (rowB >> 1) & 3;
    const uint32_t chB = (uint32_t)(mi4 & 1);
    fa.cswB[0] = ((0 + chB) ^ rmB) << 4;
    fa.cswB[1] = ((2 + chB) ^ rmB) << 4;
    return fa;
}

// =============================================================================
// prep: w1, w2 -> half scratch; zero g_part.
// =============================================================================
__global__ __launch_bounds__(256) void prep_kernel(
    const float* __restrict__ w1, const float* __restrict__ w2)
{
    const int i = blockIdx.x * 256 + threadIdx.x;   // 786432 / 4 threads
    {
        const float4 v = *(const float4*)(w1 + (size_t)i * 4);
        __half2 h0 = __floats2half2_rn(v.x, v.y);
        __half2 h1 = __floats2half2_rn(v.z, v.w);
        *(__half2*)(g_w1h + (size_t)i * 4)     = h0;
        *(__half2*)(g_w1h + (size_t)i * 4 + 2) = h1;
    }
    {
        const float4 v = *(const float4*)(w2 + (size_t)i * 4);
        __half2 h0 = __floats2half2_rn(v.x, v.y);
        __half2 h1 = __floats2half2_rn(v.z, v.w);
        *(__half2*)(g_w2h + (size_t)i * 4)     = h0;
        *(__half2*)(g_w2h + (size_t)i * 4 + 2) = h1;
    }
    if (i < BATCH * IDIM / 4)
        *(float4*)(g_part + (size_t)i * 4) = make_float4(0.f, 0.f, 0.f, 0.f);
}

// =============================================================================
// conv1d depthwise (K=7) + bias + LayerNorm over C; store half.
// =============================================================================
__global__ __launch_bounds__(256) void convln_kernel(
    const float* __restrict__ x, const float* __restrict__ dw_w,
    const float* __restrict__ dw_b, const float* __restrict__ ln_g,
    const float* __restrict__ ln_b)
{
    __shared__ float s[DIM][17];
    const int b  = blockIdx.y;
    const int t0 = blockIdx.x * 16;
    const int tid = threadIdx.x;

    for (int idx = tid; idx < DIM * 16; idx += 256) {
        const int c  = idx >> 4;
        const int tl = idx & 15;
        const int t  = t0 + tl;
        const float* xr = x + ((size_t)b * DIM + c) * TLEN;
        const float* wc = dw_w + c * 7;
        float acc = dw_b[c];
        #pragma unroll
        for (int k = 0; k < 7; k++) {
            const int tt = t + k - 3;
            if (tt >= 0 && tt < TLEN) acc += xr[tt] * wc[k];
        }
        s[c][tl] = acc;
    }
    __syncthreads();

    const int wid = tid >> 5, lane = tid & 31;
    #pragma unroll
    for (int rr = 0; rr < 2; rr++) {
        const int tl = wid + rr * 8;
        float sum = 0.f, sq = 0.f;
        #pragma unroll
        for (int c = lane; c < DIM; c += 32) {
            const float v = s[c][tl];
            sum += v; sq += v * v;
        }
        #pragma unroll
        for (int o = 16; o; o >>= 1) {
            sum += __shfl_xor_sync(0xffffffffu, sum, o);
            sq  += __shfl_xor_sync(0xffffffffu, sq,  o);
        }
        const float mu  = sum * (1.f / DIM);
        const float var = sq * (1.f / DIM) - mu * mu;
        const float rs  = rsqrtf(var + 1e-6f);
        __half* yr = g_y + ((size_t)b * TLEN + (t0 + tl)) * DIM;
        for (int c = lane; c < DIM; c += 32)
            yr[c] = __float2half_rn((s[c][tl] - mu) * rs * ln_g[c] + ln_b[c]);
    }
}

// =============================================================================
// GEMM1: h = gelu(y @ w1^T + b1); fused GRN sum-of-squares.
// =============================================================================
__global__ void __launch_bounds__(256, 2) gemm1_kernel(
    const float* __restrict__ b1)
{
    extern __shared__ char smem[];
    const uint32_t sb = smem_u32(smem);
    const int tid = threadIdx.x;
    const int warp = tid >> 5, lane = tid & 31;
    const int wm = warp & 3, wn = warp >> 2;
    const int n0 = blockIdx.x * 128;
    const int m0 = blockIdx.y * 128;
    const int K = DIM, NKT = DIM / BK;   // 16

    const __half* Ag = g_y   + (size_t)m0 * K;
    const __half* Bg = g_w1h + (size_t)n0 * K;
    const FragAddr fa = make_frag_addr(warp, lane);

    #pragma unroll
    for (int st = 0; st < STAGES - 1; st++) {
        issue_stage(sb, st, Ag, Bg, st, tid, K);
        CP_COMMIT();
    }

    float acc[2][8][4] = {};
    for (int kt = 0; kt < NKT; kt++) {
        CP_WAIT(STAGES - 2);
        __syncthreads();
        const int pf = kt + STAGES - 1;
        if (pf < NKT) issue_stage(sb, pf % STAGES, Ag, Bg, pf, tid, K);
        CP_COMMIT();
        const uint32_t abase = sb + (kt % STAGES) * STAGE_BYTES;
        compute_kiter<false>(abase, abase + 8192, fa.offA0, fa.cswA, fa.offB0, fa.cswB, 0, acc);
    }
    CP_WAIT(0);

    // epilogue: bias + exact GELU, half-round (store value == sumsq value)
    const int r4 = lane >> 2, c4 = lane & 3;
    #pragma unroll
    for (int mi = 0; mi < 2; mi++) {
        #pragma unroll
        for (int j = 0; j < 8; j++) {
            const int n = n0 + wn * 64 + j * 8 + c4 * 2;
            const float bv0 = b1[n], bv1 = b1[n + 1];
            acc[mi][j][0] = __half2float(__float2half_rn(gelu_exact(acc[mi][j][0] + bv0)));
            acc[mi][j][1] = __half2float(__float2half_rn(gelu_exact(acc[mi][j][1] + bv1)));
            acc[mi][j][2] = __half2float(__float2half_rn(gelu_exact(acc[mi][j][2] + bv0)));
            acc[mi][j][3] = __half2float(__float2half_rn(gelu_exact(acc[mi][j][3] + bv1)));
        }
    }
    #pragma unroll
    for (int mi = 0; mi < 2; mi++) {
        const int m = m0 + wm * 32 + mi * 16 + r4;
        #pragma unroll
        for (int j = 0; j < 8; j++) {
            const int n = n0 + wn * 64 + j * 8 + c4 * 2;
            *(__half2*)(g_h + (size_t)m * IDIM + n) =
                __floats2half2_rn(acc[mi][j][0], acc[mi][j][1]);
            *(__half2*)(g_h + (size_t)(m + 8) * IDIM + n) =
                __floats2half2_rn(acc[mi][j][2], acc[mi][j][3]);
        }
    }
    const int b = m0 >> 11;
    #pragma unroll
    for (int j = 0; j < 8; j++) {
        float s0 = acc[0][j][0] * acc[0][j][0] + acc[0][j][2] * acc[0][j][2]
                 + acc[1][j][0] * acc[1][j][0] + acc[1][j][2] * acc[1][j][2];
        float s1 = acc[0][j][1] * acc[0][j][1] + acc[0][j][3] * acc[0][j][3]
                 + acc[1][j][1] * acc[1][j][1] + acc[1][j][3] * acc[1][j][3];
        #pragma unroll
        for (int o = 4; o < 32; o <<= 1) {
            s0 += __shfl_xor_sync(0xffffffffu, s0, o);
            s1 += __shfl_xor_sync(0xffffffffu, s1, o);
        }
        if (lane < 4) {
            const int n = n0 + wn * 64 + j * 8 + lane * 2;
            atomicAdd(&g_part[b * IDIM + n],     s0);
            atomicAdd(&g_part[b * IDIM + n + 1], s1);
        }
    }
}

// =============================================================================
// GRN scale -> half
// =============================================================================
__global__ __launch_bounds__(256) void grn_scale_kernel(const float* __restrict__ grn_g)
{
    __shared__ float sgx[IDIM];
    __shared__ float red[256];
    const int b = blockIdx.x;
    const int tid = threadIdx.x;
    float local = 0.f;
    for (int i = tid; i < IDIM; i += 256) {
        const float gx = sqrtf(g_part[b * IDIM + i]);
        sgx[i] = gx;
        local += gx;
    }
    red[tid] = local;
    __syncthreads();
    for (int o = 128; o; o >>= 1) {
        if (tid < o) red[tid] += red[tid + o];
        __syncthreads();
    }
    const float mean = red[0] * (1.f / IDIM);
    const float inv  = 1.f / (mean + 1e-6f);
    for (int i = tid; i < IDIM; i += 256)
        g_scale[b * IDIM + i] = __float2half_rn(grn_g[i] * sgx[i] * inv + 1.0f);
}

// =============================================================================
// gw2[c] = sum_i grn_b[i] * w2[c][i]
// =============================================================================
__global__ __launch_bounds__(256) void gw2_kernel(const float* __restrict__ grn_b)
{
    const int w = (blockIdx.x * 256 + threadIdx.x) >> 5;   // 0..511
    const int lane = threadIdx.x & 31;
    const __half* row = g_w2h + (size_t)w * IDIM;
    float s = 0.f;
    for (int i = lane; i < IDIM; i += 32) s += __half2float(row[i]) * grn_b[i];
    #pragma unroll
    for (int o = 16; o; o >>= 1) s += __shfl_xor_sync(0xffffffffu, s, o);
    if (lane == 0) g_gw2[w] = s;
}

// =============================================================================
// GEMM2: out = x + T( (h*scale) @ w2^T + gw2 + b2 )
// =============================================================================
__global__ void __launch_bounds__(256, 2) gemm2_kernel(
    const float* __restrict__ b2v, const float* __restrict__ xres,
    float* __restrict__ out)
{
    extern __shared__ char smem[];
    const uint32_t sb = smem_u32(smem);
    const int tid = threadIdx.x;
    const int warp = tid >> 5, lane = tid & 31;
    const int wm = warp & 3, wn = warp >> 2;
    const int n0 = blockIdx.x * 128;
    const int m0 = blockIdx.y * 128;
    const int bb = m0 >> 11;
    const int t0 = m0 & (TLEN - 1);
    const int K = IDIM, NKT = IDIM / BK;   // 48

    const __half* Ag = g_h   + (size_t)m0 * K;
    const __half* Bg = g_w2h + (size_t)n0 * K;
    const FragAddr fa = make_frag_addr(warp, lane);

    // GRN scale row (half, 3KB) after stage buffers
    const uint32_t s_base = sb + STAGES * STAGE_BYTES;
    {
        const __half* Sc = g_scale + (size_t)bb * IDIM;
        for (int i = tid; i < IDIM / 8; i += 256)
            *(float4*)(smem + STAGES * STAGE_BYTES + i * 16) = *(const float4*)(Sc + i * 8);
    }

    #pragma unroll
    for (int st = 0; st < STAGES - 1; st++) {
        issue_stage(sb, st, Ag, Bg, st, tid, K);
        CP_COMMIT();
    }

    float acc[2][8][4] = {};
    const int c4 = lane & 3;
    for (int kt = 0; kt < NKT; kt++) {
        CP_WAIT(STAGES - 2);
        __syncthreads();
        const int pf = kt + STAGES - 1;
        if (pf < NKT) issue_stage(sb, pf % STAGES, Ag, Bg, pf, tid, K);
        CP_COMMIT();
        const uint32_t abase = sb + (kt % STAGES) * STAGE_BYTES;
        const uint32_t s_addr = s_base + kt * 64 + c4 * 4;
        compute_kiter<true>(abase, abase + 8192, fa.offA0, fa.cswA, fa.offB0, fa.cswB, s_addr, acc);
    }
    CP_WAIT(0);
    __syncthreads();

    // epilogue: transpose via smem (alias stage buffers), residual + biases.
    float (*trans)[132] = (float(*)[132])smem;   // [32][132]
    const int r4 = lane >> 2;

    #pragma unroll
    for (int q = 0; q < 4; q++) {
        if (wn == (q >> 1)) {
            const int jb = (q & 1) * 4;
            #pragma unroll
            for (int jl = 0; jl < 4; jl++) {
                const int cl = (jb + jl) * 8 + c4 * 2 - (q & 1) * 32;  // 0..31
                #pragma unroll
                for (int mi = 0; mi < 2; mi++) {
                    const int ml = wm * 32 + mi * 16 + r4;
                    trans[cl][ml]         = acc[mi][jb + jl][0];
                    trans[cl + 1][ml]     = acc[mi][jb + jl][1];
                    trans[cl][ml + 8]     = acc[mi][jb + jl][2];
                    trans[cl + 1][ml + 8] = acc[mi][jb + jl][3];
                }
            }
        }
        __syncthreads();
        for (int r = tid; r < 32 * 128; r += 256) {
            const int cl = r >> 7, tl = r & 127;
            const int c = n0 + 32 * q + cl;
            const size_t oi = ((size_t)(bb * DIM + c)) * TLEN + t0 + tl;
            out[oi] = xres[oi] + trans[cl][tl] + b2v[c] + g_gw2[c];
        }
        __syncthreads();
    }
}

// =============================================================================
// Launch
// =============================================================================
extern "C" void kernel_launch(void* const* d_in, const int* in_sizes, int n_in,
                              void* d_out, int out_size)
{
    const float* x     = (const float*)d_in[0];
    const float* dw_w  = (const float*)d_in[1];
    const float* dw_b  = (const float*)d_in[2];
    const float* ln_g  = (const float*)d_in[3];
    const float* ln_b  = (const float*)d_in[4];
    const float* w1    = (const float*)d_in[5];
    const float* b1    = (const float*)d_in[6];
    const float* grn_g = (const float*)d_in[7];
    const float* grn_b = (const float*)d_in[8];
    const float* w2    = (const float*)d_in[9];
    const float* b2    = (const float*)d_in[10];
    float* out = (float*)d_out;

    const int smem1 = STAGES * STAGE_BYTES;                 // 64 KB
    const int smem2 = STAGES * STAGE_BYTES + IDIM * 2;      // 64 KB + 3 KB
    cudaFuncSetAttribute(gemm1_kernel, cudaFuncAttributeMaxDynamicSharedMemorySize, smem1);
    cudaFuncSetAttribute(gemm2_kernel, cudaFuncAttributeMaxDynamicSharedMemorySize, smem2);

    prep_kernel<<<768, 256>>>(w1, w2);
    convln_kernel<<<dim3(TLEN / 16, BATCH), 256>>>(x, dw_w, dw_b, ln_g, ln_b);
    gemm1_kernel<<<dim3(IDIM / 128, MTOT / 128), 256, smem1>>>(b1);
    grn_scale_kernel<<<BATCH, 256>>>(grn_g);
    gw2_kernel<<<64, 256>>>(grn_b);
    gemm2_kernel<<<dim3(DIM / 128, MTOT / 128), 256, smem2>>>(b2, x, out);
}

// round 6
// speedup vs baseline: 4.8004x; 1.0387x over previous
#include <cuda_runtime.h>
#include <cuda_fp16.h>
#include <math.h>
#include <stdint.h>

#define DIM   512
#define IDIM  1536
#define BATCH 16
#define TLEN  2048
#define MTOT  (BATCH * TLEN)   // 32768

#define STAGES      4
#define STAGE_BYTES 16384      // A tile 8KB + B tile 8KB (128 x 32 halves each)
#define BK          32
#define PGRID       296        // persistent grid: 2 CTAs x 148 SMs

// gemm2 smem extras
#define SC_OFF     (STAGES * STAGE_BYTES)            // 2 x 3KB scale rows
#define TRANS_OFF  (SC_OFF + 2 * 3072)               // 32x132 f32 transpose buf
#define SMEM2      (TRANS_OFF + 32 * 132 * 4)
#define SMEM1      (STAGES * STAGE_BYTES)

// ---------------- scratch (static __device__, no allocations) ----------------
__device__ __half g_y[(size_t)MTOT * DIM];
__device__ __half g_h[(size_t)MTOT * IDIM];
__device__ __half g_w1h[(size_t)IDIM * DIM];
__device__ __half g_w2h[(size_t)DIM * IDIM];
__device__ float  g_part[BATCH * IDIM];
__device__ __half g_scale[BATCH * IDIM];
__device__ float  g_gw2[DIM];

// =============================================================================
// helpers
// =============================================================================
__device__ __forceinline__ float gelu_fast(float v) {
    // exact-erf GELU via Abramowitz-Stegun 7.1.26 (|err| <= 1.5e-7)
    const float x  = v * 0.70710678118654752f;
    const float ax = fabsf(x);
    const float t  = __fdividef(1.0f, fmaf(0.3275911f, ax, 1.0f));
    float p = fmaf(t, 1.061405429f, -1.453152027f);
    p = fmaf(t, p, 1.421413741f);
    p = fmaf(t, p, -0.284496736f);
    p = fmaf(t, p, 0.254829592f);
    p *= t;
    const float e = __expf(-x * x);
    float erfv = fmaf(-p, e, 1.0f);
    erfv = copysignf(erfv, x);
    return 0.5f * v * (1.0f + erfv);
}
__device__ __forceinline__ uint32_t smem_u32(const void* p) {
    uint32_t a;
    asm("{ .reg .u64 t; cvta.to.shared.u64 t, %1; cvt.u32.u64 %0, t; }"
        : "=r"(a) : "l"(p));
    return a;
}
__device__ __forceinline__ void cp_async16(uint32_t dst, const void* src) {
    asm volatile("cp.async.cg.shared.global [%0], [%1], 16;" :: "r"(dst), "l"(src));
}
#define CP_COMMIT() asm volatile("cp.async.commit_group;" ::: "memory")
#define CP_WAIT(n)  asm volatile("cp.async.wait_group %0;" :: "n"(n) : "memory")

__device__ __forceinline__ void ldsm_x4(uint32_t* d, uint32_t addr) {
    asm volatile("ldmatrix.sync.aligned.m8n8.x4.shared.b16 {%0,%1,%2,%3}, [%4];"
                 : "=r"(d[0]), "=r"(d[1]), "=r"(d[2]), "=r"(d[3]) : "r"(addr));
}
__device__ __forceinline__ uint32_t lds_u32(uint32_t a) {
    uint32_t v;
    asm volatile("ld.shared.b32 %0, [%1];" : "=r"(v) : "r"(a));
    return v;
}
__device__ __forceinline__ uint32_t hmul2(uint32_t a, uint32_t s) {
    uint32_t o;
    asm("mul.rn.f16x2 %0, %1, %2;" : "=r"(o) : "r"(a), "r"(s));
    return o;
}
__device__ __forceinline__ void mma_f16(float* c, const uint32_t* a, const uint32_t* b) {
    asm volatile(
        "mma.sync.aligned.m16n8k16.row.col.f32.f16.f16.f32 "
        "{%0,%1,%2,%3}, {%4,%5,%6,%7}, {%8,%9}, {%0,%1,%2,%3};"
        : "+f"(c[0]), "+f"(c[1]), "+f"(c[2]), "+f"(c[3])
        : "r"(a[0]), "r"(a[1]), "r"(a[2]), "r"(a[3]), "r"(b[0]), "r"(b[1]));
}

__device__ __forceinline__ void issue_stage(
    uint32_t sb, int st, const __half* Ag, const __half* Bg, int kt, int tid, int K)
{
    const uint32_t base = sb + st * STAGE_BYTES;
    #pragma unroll
    for (int q = 0; q < 2; q++) {
        const int cid = tid + q * 256;
        const int r = cid >> 2, c = cid & 3;
        const uint32_t so = (uint32_t)(r * 64 + ((c ^ ((r >> 1) & 3)) << 4));
        cp_async16(base + so,        Ag + (size_t)r * K + kt * BK + c * 8);
        cp_async16(base + 8192 + so, Bg + (size_t)r * K + kt * BK + c * 8);
    }
}

template<bool SCALE>
__device__ __forceinline__ void compute_kiter(
    uint32_t abase, uint32_t bbase,
    uint32_t offA0, const uint32_t* cswA,
    uint32_t offB0, const uint32_t* cswB,
    uint32_t s_addr, float acc[2][8][4])
{
    #pragma unroll
    for (int ks = 0; ks < 2; ks++) {
        uint32_t af[2][4];
        ldsm_x4(af[0], abase + offA0 + cswA[ks]);
        ldsm_x4(af[1], abase + offA0 + 1024 + cswA[ks]);
        if (SCALE) {
            const uint32_t slo = lds_u32(s_addr + ks * 32);
            const uint32_t shi = lds_u32(s_addr + ks * 32 + 16);
            #pragma unroll
            for (int mi = 0; mi < 2; mi++) {
                af[mi][0] = hmul2(af[mi][0], slo);
                af[mi][1] = hmul2(af[mi][1], slo);
                af[mi][2] = hmul2(af[mi][2], shi);
                af[mi][3] = hmul2(af[mi][3], shi);
            }
        }
        uint32_t bf[4][4];
        #pragma unroll
        for (int q = 0; q < 4; q++)
            ldsm_x4(bf[q], bbase + offB0 + q * 1024 + cswB[ks]);
        #pragma unroll
        for (int mi = 0; mi < 2; mi++)
            #pragma unroll
            for (int j = 0; j < 8; j++)
                mma_f16(acc[mi][j], af[mi], &bf[j >> 1][(j & 1) * 2]);
    }
}

struct FragAddr {
    uint32_t offA0, offB0;
    uint32_t cswA[2], cswB[2];
};
__device__ __forceinline__ FragAddr make_frag_addr(int warp, int lane) {
    FragAddr fa;
    const int wm = warp & 3, wn = warp >> 2;
    const int mi4 = lane >> 3, rloc = lane & 7;
    const int rowA = wm * 32 + (mi4 & 1) * 8 + rloc;
    fa.offA0 = rowA * 64;
    const uint32_t rmA = (rowA >> 1) & 3;
    const uint32_t chA = (uint32_t)(mi4 >> 1);
    fa.cswA[0] = ((0 + chA) ^ rmA) << 4;
    fa.cswA[1] = ((2 + chA) ^ rmA) << 4;
    const int rowB = wn * 64 + (mi4 >> 1) * 8 + rloc;
    fa.offB0 = rowB * 64;
    const uint32_t rmB = (rowB >> 1) & 3;
    const uint32_t chB = (uint32_t)(mi4 & 1);
    fa.cswB[0] = ((0 + chB) ^ rmB) << 4;
    fa.cswB[1] = ((2 + chB) ^ rmB) << 4;
    return fa;
}

// =============================================================================
// prep: w1, w2 -> half; zero g_part.
// =============================================================================
__global__ __launch_bounds__(256) void prep_kernel(
    const float* __restrict__ w1, const float* __restrict__ w2)
{
    const int i = blockIdx.x * 256 + threadIdx.x;
    {
        const float4 v = *(const float4*)(w1 + (size_t)i * 4);
        *(__half2*)(g_w1h + (size_t)i * 4)     = __floats2half2_rn(v.x, v.y);
        *(__half2*)(g_w1h + (size_t)i * 4 + 2) = __floats2half2_rn(v.z, v.w);
    }
    {
        const float4 v = *(const float4*)(w2 + (size_t)i * 4);
        *(__half2*)(g_w2h + (size_t)i * 4)     = __floats2half2_rn(v.x, v.y);
        *(__half2*)(g_w2h + (size_t)i * 4 + 2) = __floats2half2_rn(v.z, v.w);
    }
    if (i < BATCH * IDIM / 4)
        *(float4*)(g_part + (size_t)i * 4) = make_float4(0.f, 0.f, 0.f, 0.f);
}

// =============================================================================
// conv1d depthwise (K=7) + bias + LayerNorm over C; store half.
// =============================================================================
__global__ __launch_bounds__(256) void convln_kernel(
    const float* __restrict__ x, const float* __restrict__ dw_w,
    const float* __restrict__ dw_b, const float* __restrict__ ln_g,
    const float* __restrict__ ln_b)
{
    __shared__ float s[DIM][17];
    const int b  = blockIdx.y;
    const int t0 = blockIdx.x * 16;
    const int tid = threadIdx.x;

    for (int idx = tid; idx < DIM * 16; idx += 256) {
        const int c  = idx >> 4;
        const int tl = idx & 15;
        const int t  = t0 + tl;
        const float* xr = x + ((size_t)b * DIM + c) * TLEN;
        const float* wc = dw_w + c * 7;
        float acc = dw_b[c];
        #pragma unroll
        for (int k = 0; k < 7; k++) {
            const int tt = t + k - 3;
            if (tt >= 0 && tt < TLEN) acc += xr[tt] * wc[k];
        }
        s[c][tl] = acc;
    }
    __syncthreads();

    const int wid = tid >> 5, lane = tid & 31;
    #pragma unroll
    for (int rr = 0; rr < 2; rr++) {
        const int tl = wid + rr * 8;
        float sum = 0.f, sq = 0.f;
        #pragma unroll
        for (int c = lane; c < DIM; c += 32) {
            const float v = s[c][tl];
            sum += v; sq += v * v;
        }
        #pragma unroll
        for (int o = 16; o; o >>= 1) {
            sum += __shfl_xor_sync(0xffffffffu, sum, o);
            sq  += __shfl_xor_sync(0xffffffffu, sq,  o);
        }
        const float mu  = sum * (1.f / DIM);
        const float var = sq * (1.f / DIM) - mu * mu;
        const float rs  = rsqrtf(var + 1e-6f);
        __half* yr = g_y + ((size_t)b * TLEN + (t0 + tl)) * DIM;
        for (int c = lane; c < DIM; c += 32)
            yr[c] = __float2half_rn((s[c][tl] - mu) * rs * ln_g[c] + ln_b[c]);
    }
}

// =============================================================================
// GEMM1 (persistent, continuous pipeline): h = gelu(y @ w1^T + b1) + GRN sumsq
// =============================================================================
__global__ void __launch_bounds__(256, 2) gemm1_kernel(const float* __restrict__ b1)
{
    extern __shared__ char smem[];
    const uint32_t sb = smem_u32(smem);
    const int tid = threadIdx.x;
    const int warp = tid >> 5, lane = tid & 31;
    const int wm = warp & 3, wn = warp >> 2;
    const FragAddr fa = make_frag_addr(warp, lane);
    const int NKT = DIM / BK;                     // 16
    const int NT  = (IDIM / 128) * (MTOT / 128);  // 3072
    const int ntile = (NT - (int)blockIdx.x + (int)gridDim.x - 1) / (int)gridDim.x;
    if (ntile <= 0) return;
    const int total = ntile * NKT;

    // prefetch cursor
    int pt = 0, pk = 0;
    const __half *Ap = g_y   + (size_t)(((int)blockIdx.x / 12) * 128) * DIM;
    const __half *Bp = g_w1h + (size_t)(((int)blockIdx.x % 12) * 128) * DIM;

    #pragma unroll
    for (int s = 0; s < STAGES - 1; s++) {
        if (s < total) {
            issue_stage(sb, s & 3, Ap, Bp, pk, tid, DIM);
            if (++pk == NKT) {
                pk = 0; pt++;
                if (pt < ntile) {
                    const int t = (int)blockIdx.x + pt * (int)gridDim.x;
                    Ap = g_y + (size_t)((t / 12) * 128) * DIM;
                    Bp = g_w1h + (size_t)((t % 12) * 128) * DIM;
                }
            }
        }
        CP_COMMIT();
    }

    int ct = 0, kt = 0;
    int m0 = ((int)blockIdx.x / 12) * 128, n0 = ((int)blockIdx.x % 12) * 128;
    float acc[2][8][4] = {};
    const int r4 = lane >> 2, c4 = lane & 3;

    for (int g = 0; g < total; g++) {
        CP_WAIT(STAGES - 2);
        __syncthreads();
        if (g + STAGES - 1 < total) {
            issue_stage(sb, (g + STAGES - 1) & 3, Ap, Bp, pk, tid, DIM);
            if (++pk == NKT) {
                pk = 0; pt++;
                if (pt < ntile) {
                    const int t = (int)blockIdx.x + pt * (int)gridDim.x;
                    Ap = g_y + (size_t)((t / 12) * 128) * DIM;
                    Bp = g_w1h + (size_t)((t % 12) * 128) * DIM;
                }
            }
        }
        CP_COMMIT();
        const uint32_t abase = sb + (g & 3) * STAGE_BYTES;
        compute_kiter<false>(abase, abase + 8192, fa.offA0, fa.cswA, fa.offB0, fa.cswB, 0, acc);

        if (++kt == NKT) {
            kt = 0;
            // ---- epilogue: bias + GELU, half-round, store, fused sumsq ----
            #pragma unroll
            for (int mi = 0; mi < 2; mi++) {
                #pragma unroll
                for (int j = 0; j < 8; j++) {
                    const int n = n0 + wn * 64 + j * 8 + c4 * 2;
                    const float bv0 = b1[n], bv1 = b1[n + 1];
                    acc[mi][j][0] = __half2float(__float2half_rn(gelu_fast(acc[mi][j][0] + bv0)));
                    acc[mi][j][1] = __half2float(__float2half_rn(gelu_fast(acc[mi][j][1] + bv1)));
                    acc[mi][j][2] = __half2float(__float2half_rn(gelu_fast(acc[mi][j][2] + bv0)));
                    acc[mi][j][3] = __half2float(__float2half_rn(gelu_fast(acc[mi][j][3] + bv1)));
                }
            }
            #pragma unroll
            for (int mi = 0; mi < 2; mi++) {
                const int m = m0 + wm * 32 + mi * 16 + r4;
                #pragma unroll
                for (int j = 0; j < 8; j++) {
                    const int n = n0 + wn * 64 + j * 8 + c4 * 2;
                    *(__half2*)(g_h + (size_t)m * IDIM + n) =
                        __floats2half2_rn(acc[mi][j][0], acc[mi][j][1]);
                    *(__half2*)(g_h + (size_t)(m + 8) * IDIM + n) =
                        __floats2half2_rn(acc[mi][j][2], acc[mi][j][3]);
                }
            }
            const int b = m0 >> 11;
            #pragma unroll
            for (int j = 0; j < 8; j++) {
                float s0 = acc[0][j][0] * acc[0][j][0] + acc[0][j][2] * acc[0][j][2]
                         + acc[1][j][0] * acc[1][j][0] + acc[1][j][2] * acc[1][j][2];
                float s1 = acc[0][j][1] * acc[0][j][1] + acc[0][j][3] * acc[0][j][3]
                         + acc[1][j][1] * acc[1][j][1] + acc[1][j][3] * acc[1][j][3];
                #pragma unroll
                for (int o = 4; o < 32; o <<= 1) {
                    s0 += __shfl_xor_sync(0xffffffffu, s0, o);
                    s1 += __shfl_xor_sync(0xffffffffu, s1, o);
                }
                if (lane < 4) {
                    const int n = n0 + wn * 64 + j * 8 + lane * 2;
                    atomicAdd(&g_part[b * IDIM + n],     s0);
                    atomicAdd(&g_part[b * IDIM + n + 1], s1);
                }
            }
            #pragma unroll
            for (int mi = 0; mi < 2; mi++)
                #pragma unroll
                for (int j = 0; j < 8; j++)
                    #pragma unroll
                    for (int q = 0; q < 4; q++) acc[mi][j][q] = 0.f;
            if (++ct < ntile) {
                const int t = (int)blockIdx.x + ct * (int)gridDim.x;
                m0 = (t / 12) * 128; n0 = (t % 12) * 128;
            }
        }
    }
}

// =============================================================================
// GRN scale + gw2 combined (blocks 0-15: scale; 16-79: gw2)
// =============================================================================
__global__ __launch_bounds__(256) void grn_combo_kernel(
    const float* __restrict__ grn_g, const float* __restrict__ grn_b)
{
    if (blockIdx.x < 16) {
        __shared__ float sgx[IDIM];
        __shared__ float red[256];
        const int b = blockIdx.x;
        const int tid = threadIdx.x;
        float local = 0.f;
        for (int i = tid; i < IDIM; i += 256) {
            const float gx = sqrtf(g_part[b * IDIM + i]);
            sgx[i] = gx;
            local += gx;
        }
        red[tid] = local;
        __syncthreads();
        for (int o = 128; o; o >>= 1) {
            if (tid < o) red[tid] += red[tid + o];
            __syncthreads();
        }
        const float mean = red[0] * (1.f / IDIM);
        const float inv  = 1.f / (mean + 1e-6f);
        for (int i = tid; i < IDIM; i += 256)
            g_scale[b * IDIM + i] = __float2half_rn(grn_g[i] * sgx[i] * inv + 1.0f);
    } else {
        const int w = (blockIdx.x - 16) * 8 + (threadIdx.x >> 5);   // 0..511
        const int lane = threadIdx.x & 31;
        const __half* row = g_w2h + (size_t)w * IDIM;
        float s = 0.f;
        for (int i = lane; i < IDIM; i += 32) s += __half2float(row[i]) * grn_b[i];
        #pragma unroll
        for (int o = 16; o; o >>= 1) s += __shfl_xor_sync(0xffffffffu, s, o);
        if (lane == 0) g_gw2[w] = s;
    }
}

// =============================================================================
// GEMM2 (persistent, continuous pipeline): out = x + T((h*scale) @ w2^T + gw2 + b2)
// =============================================================================
__global__ void __launch_bounds__(256, 2) gemm2_kernel(
    const float* __restrict__ b2v, const float* __restrict__ xres,
    float* __restrict__ out)
{
    extern __shared__ char smem[];
    const uint32_t sb = smem_u32(smem);
    const int tid = threadIdx.x;
    const int warp = tid >> 5, lane = tid & 31;
    const int wm = warp & 3, wn = warp >> 2;
    const FragAddr fa = make_frag_addr(warp, lane);
    const int NKT = IDIM / BK;                   // 48
    const int NT  = (DIM / 128) * (MTOT / 128);  // 1024
    const int ntile = (NT - (int)blockIdx.x + (int)gridDim.x - 1) / (int)gridDim.x;
    if (ntile <= 0) return;
    const int total = ntile * NKT;

    // prefetch cursor (scale row fetched with each tile's first stage)
    int pt = 0, pk = 0;
    const __half *Ap, *Bp;
    {
        const int t = (int)blockIdx.x;
        Ap = g_h   + (size_t)((t / 4) * 128) * IDIM;
        Bp = g_w2h + (size_t)((t % 4) * 128) * IDIM;
    }
    #pragma unroll
    for (int s = 0; s < STAGES - 1; s++) {
        if (s < total) {
            if (pk == 0 && tid < 192) {
                const int t = (int)blockIdx.x + pt * (int)gridDim.x;
                const int bbp = ((t / 4) * 128) >> 11;
                cp_async16(sb + SC_OFF + (pt & 1) * 3072 + tid * 16,
                           g_scale + (size_t)bbp * IDIM + tid * 8);
            }
            issue_stage(sb, s & 3, Ap, Bp, pk, tid, IDIM);
            if (++pk == NKT) {
                pk = 0; pt++;
                if (pt < ntile) {
                    const int t = (int)blockIdx.x + pt * (int)gridDim.x;
                    Ap = g_h + (size_t)((t / 4) * 128) * IDIM;
                    Bp = g_w2h + (size_t)((t % 4) * 128) * IDIM;
                }
            }
        }
        CP_COMMIT();
    }

    int ct = 0, kt = 0;
    int m0 = (((int)blockIdx.x) / 4) * 128, n0 = (((int)blockIdx.x) % 4) * 128;
    float acc[2][8][4] = {};
    const int r4 = lane >> 2, c4 = lane & 3;

    for (int g = 0; g < total; g++) {
        CP_WAIT(STAGES - 2);
        __syncthreads();
        if (g + STAGES - 1 < total) {
            if (pk == 0 && tid < 192) {
                const int t = (int)blockIdx.x + pt * (int)gridDim.x;
                const int bbp = ((t / 4) * 128) >> 11;
                cp_async16(sb + SC_OFF + (pt & 1) * 3072 + tid * 16,
                           g_scale + (size_t)bbp * IDIM + tid * 8);
            }
            issue_stage(sb, (g + STAGES - 1) & 3, Ap, Bp, pk, tid, IDIM);
            if (++pk == NKT) {
                pk = 0; pt++;
                if (pt < ntile) {
                    const int t = (int)blockIdx.x + pt * (int)gridDim.x;
                    Ap = g_h + (size_t)((t / 4) * 128) * IDIM;
                    Bp = g_w2h + (size_t)((t % 4) * 128) * IDIM;
                }
            }
        }
        CP_COMMIT();
        const uint32_t abase = sb + (g & 3) * STAGE_BYTES;
        const uint32_t s_addr = sb + SC_OFF + (ct & 1) * 3072 + kt * 64 + c4 * 4;
        compute_kiter<true>(abase, abase + 8192, fa.offA0, fa.cswA, fa.offB0, fa.cswB, s_addr, acc);

        if (++kt == NKT) {
            kt = 0;
            // ---- epilogue: transpose via dedicated smem buf, residual+bias ----
            const int bb = m0 >> 11;
            const int t0 = m0 & (TLEN - 1);
            float (*trans)[132] = (float(*)[132])(smem + TRANS_OFF);
            __syncthreads();
            #pragma unroll
            for (int q = 0; q < 4; q++) {
                if (wn == (q >> 1)) {
                    const int jb = (q & 1) * 4;
                    #pragma unroll
                    for (int jl = 0; jl < 4; jl++) {
                        const int cl = (jb + jl) * 8 + c4 * 2 - (q & 1) * 32;
                        #pragma unroll
                        for (int mi = 0; mi < 2; mi++) {
                            const int ml = wm * 32 + mi * 16 + r4;
                            trans[cl][ml]         = acc[mi][jb + jl][0];
                            trans[cl + 1][ml]     = acc[mi][jb + jl][1];
                            trans[cl][ml + 8]     = acc[mi][jb + jl][2];
                            trans[cl + 1][ml + 8] = acc[mi][jb + jl][3];
                        }
                    }
                }
                __syncthreads();
                for (int r = tid; r < 32 * 128; r += 256) {
                    const int cl = r >> 7, tl = r & 127;
                    const int c = n0 + 32 * q + cl;
                    const size_t oi = ((size_t)(bb * DIM + c)) * TLEN + t0 + tl;
                    out[oi] = xres[oi] + trans[cl][tl] + b2v[c] + g_gw2[c];
                }
                __syncthreads();
            }
            #pragma unroll
            for (int mi = 0; mi < 2; mi++)
                #pragma unroll
                for (int j = 0; j < 8; j++)
                    #pragma unroll
                    for (int q = 0; q < 4; q++) acc[mi][j][q] = 0.f;
            if (++ct < ntile) {
                const int t = (int)blockIdx.x + ct * (int)gridDim.x;
                m0 = (t / 4) * 128; n0 = (t % 4) * 128;
            }
        }
    }
}

// =============================================================================
// Launch
// =============================================================================
extern "C" void kernel_launch(void* const* d_in, const int* in_sizes, int n_in,
                              void* d_out, int out_size)
{
    const float* x     = (const float*)d_in[0];
    const float* dw_w  = (const float*)d_in[1];
    const float* dw_b  = (const float*)d_in[2];
    const float* ln_g  = (const float*)d_in[3];
    const float* ln_b  = (const float*)d_in[4];
    const float* w1    = (const float*)d_in[5];
    const float* b1    = (const float*)d_in[6];
    const float* grn_g = (const float*)d_in[7];
    const float* grn_b = (const float*)d_in[8];
    const float* w2    = (const float*)d_in[9];
    const float* b2    = (const float*)d_in[10];
    float* out = (float*)d_out;

    cudaFuncSetAttribute(gemm1_kernel, cudaFuncAttributeMaxDynamicSharedMemorySize, SMEM1);
    cudaFuncSetAttribute(gemm2_kernel, cudaFuncAttributeMaxDynamicSharedMemorySize, SMEM2);

    prep_kernel<<<768, 256>>>(w1, w2);
    convln_kernel<<<dim3(TLEN / 16, BATCH), 256>>>(x, dw_w, dw_b, ln_g, ln_b);
    gemm1_kernel<<<PGRID, 256, SMEM1>>>(b1);
    grn_combo_kernel<<<80, 256>>>(grn_g, grn_b);
    gemm2_kernel<<<PGRID, 256, SMEM2>>>(b2, x, out);
}